// round 6
// baseline (speedup 1.0000x reference)
#include <cuda_runtime.h>
#include <cuda_bf16.h>
#include <cstdint>
#include <math.h>

#define T_   1024
#define CV_  8
#define DIM_ 2048
#define NH_  32
#define BMM_ 2048   // NH*HD

// ---------------------------------------------------------------------------
// Scratch (device globals; no allocation allowed)
// ---------------------------------------------------------------------------
__device__ float g_q[T_ * BMM_];            // 8 MB
__device__ float g_k[T_ * CV_ * BMM_];      // 64 MB
__device__ float g_v[T_ * CV_ * BMM_];      // 64 MB
__device__ float g_att[T_ * BMM_];          // 8 MB

#define ROWS_X  T_
#define ROWS_C  (T_ * CV_)
#define ROWS_W  BMM_
__device__ __align__(16) char g_xq1[ROWS_X * DIM_],  g_xq2[ROWS_X * DIM_];
__device__ __align__(16) char g_cq1[ROWS_C * DIM_],  g_cq2[ROWS_C * DIM_];
__device__ __align__(16) char g_wqq1[ROWS_W * DIM_], g_wqq2[ROWS_W * DIM_];
__device__ __align__(16) char g_wkq1[ROWS_W * DIM_], g_wkq2[ROWS_W * DIM_];
__device__ __align__(16) char g_wvq1[ROWS_W * DIM_], g_wvq2[ROWS_W * DIM_];
__device__ __align__(16) char g_woq1[DIM_ * BMM_],   g_woq2[DIM_ * BMM_];
__device__ __align__(16) char g_aq1[T_ * BMM_],      g_aq2[T_ * BMM_];
__device__ float g_sx[ROWS_X], g_sc[ROWS_C], g_swq[ROWS_W], g_swk[ROWS_W],
                 g_swv[ROWS_W], g_swo[DIM_], g_sa[T_];

// ---------------------------------------------------------------------------
// helpers
// ---------------------------------------------------------------------------
__device__ __forceinline__ uint32_t smem_u32(const void* p) {
    uint32_t a;
    asm("{ .reg .u64 t; cvta.to.shared.u64 t, %1; cvt.u32.u64 %0, t; }"
        : "=r"(a) : "l"(p));
    return a;
}
// 64B-row swizzle: XOR 16B-chunk bits [4:5] with row bits [7:8]
__device__ __forceinline__ uint32_t swz64(uint32_t o) { return o ^ ((o >> 3) & 0x30); }

__device__ __forceinline__ void ldsm4(uint32_t& r0, uint32_t& r1, uint32_t& r2,
                                      uint32_t& r3, uint32_t a) {
    asm volatile("ldmatrix.sync.aligned.m8n8.x4.shared.b16 {%0,%1,%2,%3}, [%4];"
                 : "=r"(r0), "=r"(r1), "=r"(r2), "=r"(r3) : "r"(a));
}
__device__ __forceinline__ void imma(int* c, const uint32_t* a, const uint32_t* b) {
    asm volatile("mma.sync.aligned.m16n8k32.row.col.s32.s8.s8.s32 "
                 "{%0,%1,%2,%3}, {%4,%5,%6,%7}, {%8,%9}, {%0,%1,%2,%3};"
                 : "+r"(c[0]), "+r"(c[1]), "+r"(c[2]), "+r"(c[3])
                 : "r"(a[0]), "r"(a[1]), "r"(a[2]), "r"(a[3]), "r"(b[0]), "r"(b[1]));
}
__device__ __forceinline__ void cp16(uint32_t saddr, const void* gaddr) {
    asm volatile("cp.async.cg.shared.global [%0], [%1], 16;"
                 :: "r"(saddr), "l"(gaddr) : "memory");
}
__device__ __forceinline__ void cp_commit() {
    asm volatile("cp.async.commit_group;" ::: "memory");
}
template <int N> __device__ __forceinline__ void cp_wait() {
    asm volatile("cp.async.wait_group %0;" :: "n"(N) : "memory");
}

// ---------------------------------------------------------------------------
// Per-row 2-level int8 quantization: a = s*(a1 + a2/128), s = rowmax/127.
// One block per row (K = 2048, 256 threads, 8 elems/thread held in regs).
// ---------------------------------------------------------------------------
__global__ void __launch_bounds__(256)
quant_rows(const float* __restrict__ src, char* __restrict__ q1,
           char* __restrict__ q2, float* __restrict__ sc, int K) {
    const int row = blockIdx.x, tid = threadIdx.x;
    const float4* r4 = (const float4*)(src + (size_t)row * K);
    float4 f[2];
    f[0] = r4[tid];
    f[1] = r4[tid + 256];

    float m = 0.f;
#pragma unroll
    for (int j = 0; j < 2; j++) {
        m = fmaxf(m, fabsf(f[j].x)); m = fmaxf(m, fabsf(f[j].y));
        m = fmaxf(m, fabsf(f[j].z)); m = fmaxf(m, fabsf(f[j].w));
    }
#pragma unroll
    for (int o = 16; o; o >>= 1) m = fmaxf(m, __shfl_xor_sync(0xffffffffu, m, o));
    __shared__ float red[8];
    if ((tid & 31) == 0) red[tid >> 5] = m;
    __syncthreads();
    m = red[0];
#pragma unroll
    for (int i = 1; i < 8; i++) m = fmaxf(m, red[i]);

    const float inv = (m > 1e-30f) ? 127.f / m : 0.f;
    if (tid == 0) sc[row] = (m > 1e-30f) ? m / 127.f : 0.f;

#pragma unroll
    for (int j = 0; j < 2; j++) {
        const float qv[4] = {f[j].x * inv, f[j].y * inv, f[j].z * inv, f[j].w * inv};
        char4 c1, c2;
        float a1;
        a1 = rintf(qv[0]); c1.x = (char)(int)a1; c2.x = (char)__float2int_rn((qv[0] - a1) * 128.f);
        a1 = rintf(qv[1]); c1.y = (char)(int)a1; c2.y = (char)__float2int_rn((qv[1] - a1) * 128.f);
        a1 = rintf(qv[2]); c1.z = (char)(int)a1; c2.z = (char)__float2int_rn((qv[2] - a1) * 128.f);
        a1 = rintf(qv[3]); c1.w = (char)(int)a1; c2.w = (char)__float2int_rn((qv[3] - a1) * 128.f);
        const int idx = tid + j * 256;
        ((char4*)(q1 + (size_t)row * K))[idx] = c1;
        ((char4*)(q2 + (size_t)row * K))[idx] = c2;
    }
}

// ---------------------------------------------------------------------------
// INT8x3 GEMM: C[M,N] = diag(sA) * (A1 + A2/128)(B1 + B2/128)^T * diag(sB)
// dropping A2*B2. CTA tile 128x128, BK=64 (bytes), 8 warps (warp 64x32),
// 4-stage cp.async pipeline. int32 accumulation across all of K.
// ---------------------------------------------------------------------------
#define QBM 128
#define QBN 128
#define QBK 64
#define A1_OFF 0
#define A2_OFF 8192
#define B1_OFF 16384
#define B2_OFF 24576
#define QSTAGE 32768
#define QNST   4
#define QSMEM  (QNST * QSTAGE)   // 131072

__device__ __forceinline__ void q_load_stage(
    const char* __restrict__ A1, const char* __restrict__ A2,
    const char* __restrict__ B1, const char* __restrict__ B2,
    int bm, int bn, int K, int kc, uint32_t stg, int tid) {
#pragma unroll
    for (int j = 0; j < 2; j++) {
        const int idx = j * 256 + tid;
        const int r = idx >> 2, c = idx & 3;
        const uint32_t so = swz64((uint32_t)(r * 64 + c * 16));
        const size_t ga = (size_t)(bm + r) * K + kc + c * 16;
        const size_t gb = (size_t)(bn + r) * K + kc + c * 16;
        cp16(stg + A1_OFF + so, A1 + ga);
        cp16(stg + A2_OFF + so, A2 + ga);
        cp16(stg + B1_OFF + so, B1 + gb);
        cp16(stg + B2_OFF + so, B2 + gb);
    }
}

__global__ void __launch_bounds__(256, 1)
gemm_i8(const char* __restrict__ A1, const char* __restrict__ A2,
        const float* __restrict__ sA,
        const char* __restrict__ B1, const char* __restrict__ B2,
        const float* __restrict__ sB,
        float* __restrict__ C, int M, int N, int K) {
    extern __shared__ char sm[];
    const uint32_t sb = smem_u32(sm);
    const int tid  = threadIdx.x;
    const int lane = tid & 31;
    const int wid  = tid >> 5;
    const int wm   = wid >> 2;   // 0..1 (64-row slice)
    const int wn   = wid & 3;    // 0..3 (32-col slice)
    const int bm   = blockIdx.y * QBM;
    const int bn   = blockIdx.x * QBN;

    int hi[4][4][4], lo[4][4][4];
#pragma unroll
    for (int i = 0; i < 4; i++)
#pragma unroll
        for (int j = 0; j < 4; j++)
#pragma unroll
            for (int r = 0; r < 4; r++) { hi[i][j][r] = 0; lo[i][j][r] = 0; }

    const int NCHK = K / QBK;   // 32
    q_load_stage(A1, A2, B1, B2, bm, bn, K, 0,        sb,              tid); cp_commit();
    q_load_stage(A1, A2, B1, B2, bm, bn, K, QBK,      sb + QSTAGE,     tid); cp_commit();
    q_load_stage(A1, A2, B1, B2, bm, bn, K, 2 * QBK,  sb + 2 * QSTAGE, tid); cp_commit();

    const int lr   = (lane & 7) + ((lane >> 3) & 1) * 8;  // row within 16
    const int lc16 = lane >> 4;                           // 0/1 : 16B chunk

    for (int c = 0; c < NCHK; c++) {
        cp_wait<2>();
        __syncthreads();

        if (c + 3 < NCHK)
            q_load_stage(A1, A2, B1, B2, bm, bn, K, (c + 3) * QBK,
                         sb + (uint32_t)((c + 3) % QNST) * QSTAGE, tid);
        cp_commit();

        const uint32_t stg = sb + (uint32_t)(c % QNST) * QSTAGE;
#pragma unroll
        for (int ks = 0; ks < 2; ks++) {          // two k32 steps in BK=64
            uint32_t a1[4][4], a2[4][4];
#pragma unroll
            for (int mi = 0; mi < 4; mi++) {
                const int r = wm * 64 + mi * 16 + lr;
                const uint32_t so = swz64((uint32_t)(r * 64 + (ks * 2 + lc16) * 16));
                ldsm4(a1[mi][0], a1[mi][1], a1[mi][2], a1[mi][3], stg + A1_OFF + so);
                ldsm4(a2[mi][0], a2[mi][1], a2[mi][2], a2[mi][3], stg + A2_OFF + so);
            }
#pragma unroll
            for (int nj = 0; nj < 2; nj++) {      // two 16-row n-tiles (warp n=32)
                const int r = wn * 32 + nj * 16 + lr;
                const uint32_t so = swz64((uint32_t)(r * 64 + (ks * 2 + lc16) * 16));
                uint32_t h0, h1, h2, h3, l0, l1, l2, l3;
                ldsm4(h0, h1, h2, h3, stg + B1_OFF + so);
                ldsm4(l0, l1, l2, l3, stg + B2_OFF + so);
                uint32_t b0h[2] = {h0, h2}, b1h[2] = {h1, h3};
                uint32_t b0l[2] = {l0, l2}, b1l[2] = {l1, l3};
#pragma unroll
                for (int mi = 0; mi < 4; mi++) {
                    imma(hi[mi][nj * 2],     a1[mi], b0h);
                    imma(lo[mi][nj * 2],     a1[mi], b0l);
                    imma(lo[mi][nj * 2],     a2[mi], b0h);
                    imma(hi[mi][nj * 2 + 1], a1[mi], b1h);
                    imma(lo[mi][nj * 2 + 1], a1[mi], b1l);
                    imma(lo[mi][nj * 2 + 1], a2[mi], b1h);
                }
            }
        }
    }

    const int gr = lane >> 2, gc = (lane & 3) << 1;
#pragma unroll
    for (int mi = 0; mi < 4; mi++) {
        const int row0 = bm + wm * 64 + mi * 16 + gr;
        const float s0 = sA[row0], s1 = sA[row0 + 8];
#pragma unroll
        for (int nn = 0; nn < 4; nn++) {
            const int col = bn + wn * 32 + nn * 8 + gc;
            const float t0 = sB[col], t1 = sB[col + 1];
            const float v00 = s0 * t0 * ((float)hi[mi][nn][0] + (float)lo[mi][nn][0] * 0.0078125f);
            const float v01 = s0 * t1 * ((float)hi[mi][nn][1] + (float)lo[mi][nn][1] * 0.0078125f);
            const float v10 = s1 * t0 * ((float)hi[mi][nn][2] + (float)lo[mi][nn][2] * 0.0078125f);
            const float v11 = s1 * t1 * ((float)hi[mi][nn][3] + (float)lo[mi][nn][3] * 0.0078125f);
            *(float2*)(C + (size_t)row0 * N + col)       = make_float2(v00, v01);
            *(float2*)(C + (size_t)(row0 + 8) * N + col) = make_float2(v10, v11);
        }
    }
}

// ---------------------------------------------------------------------------
// Windowed attention. 64 keys/query: (w 0..7) x (cv 0..7), p = t+w-7;
// p<0 rows zero-padded (score 0 in softmax, zero v). RoPE drops out: q and k
// share the same per-t rotation -> dot products invariant; v unrotated.
// 256 threads = 4 (t,h) units of 64 threads.
// ---------------------------------------------------------------------------
__global__ void __launch_bounds__(256)
attn_kernel(const float* __restrict__ q, const float* __restrict__ k,
            const float* __restrict__ v, float* __restrict__ out) {
    const int t    = blockIdx.x;
    const int u    = threadIdx.x >> 6;
    const int ut   = threadIdx.x & 63;
    const int h    = blockIdx.y * 4 + u;
    const int lane = threadIdx.x & 31;
    const int wid  = threadIdx.x >> 5;

    __shared__ float4 qs4[4][16];
    __shared__ float  at[256];
    __shared__ float  wmax[8], wsum[8];

    if (ut < 16)
        qs4[u][ut] = ((const float4*)(q + (size_t)t * BMM_ + h * 64))[ut];
    __syncthreads();

    const int w = ut >> 3, cv = ut & 7, p = t + w - 7;
    float s = 0.f;
    if (p >= 0) {
        const float4* kr = (const float4*)(k + (size_t)(p * CV_ + cv) * BMM_ + h * 64);
#pragma unroll
        for (int i = 0; i < 16; i++) {
            float4 a = qs4[u][i], b = kr[i];
            s = fmaf(a.x, b.x, s); s = fmaf(a.y, b.y, s);
            s = fmaf(a.z, b.z, s); s = fmaf(a.w, b.w, s);
        }
        s *= 0.125f;   // 1/sqrt(64)
    }

    float m = s;
#pragma unroll
    for (int o = 16; o; o >>= 1) m = fmaxf(m, __shfl_xor_sync(0xffffffffu, m, o));
    if (lane == 0) wmax[wid] = m;
    __syncthreads();
    const float mx = fmaxf(wmax[u * 2], wmax[u * 2 + 1]);

    const float e = expf(s - mx);
    float sum = e;
#pragma unroll
    for (int o = 16; o; o >>= 1) sum += __shfl_xor_sync(0xffffffffu, sum, o);
    if (lane == 0) wsum[wid] = sum;
    __syncthreads();
    at[threadIdx.x] = e / (wsum[u * 2] + wsum[u * 2 + 1]);
    __syncthreads();

    float acc = 0.f;
#pragma unroll
    for (int j = 0; j < 64; j++) {
        const int pj = t + (j >> 3) - 7;
        if (pj >= 0)
            acc = fmaf(at[u * 64 + j],
                       v[(size_t)(pj * CV_ + (j & 7)) * BMM_ + h * 64 + ut],
                       acc);
    }
    out[(size_t)t * BMM_ + h * 64 + ut] = acc;
}

// ---------------------------------------------------------------------------
extern "C" void kernel_launch(void* const* d_in, const int* in_sizes, int n_in,
                              void* d_out, int out_size) {
    const float* x     = (const float*)d_in[0];
    const float* chars = (const float*)d_in[1];
    const float* wq    = (const float*)d_in[2];
    const float* wk    = (const float*)d_in[3];
    const float* wv    = (const float*)d_in[4];
    const float* wo    = (const float*)d_in[5];
    float* out = (float*)d_out;

    float *q, *k, *v, *att;
    char *xq1, *xq2, *cq1, *cq2, *wqq1, *wqq2, *wkq1, *wkq2, *wvq1, *wvq2,
         *woq1, *woq2, *aq1, *aq2;
    float *sx, *sc, *swq, *swk, *swv, *swo, *sa;
    cudaGetSymbolAddress((void**)&q,    g_q);
    cudaGetSymbolAddress((void**)&k,    g_k);
    cudaGetSymbolAddress((void**)&v,    g_v);
    cudaGetSymbolAddress((void**)&att,  g_att);
    cudaGetSymbolAddress((void**)&xq1,  g_xq1);  cudaGetSymbolAddress((void**)&xq2,  g_xq2);
    cudaGetSymbolAddress((void**)&cq1,  g_cq1);  cudaGetSymbolAddress((void**)&cq2,  g_cq2);
    cudaGetSymbolAddress((void**)&wqq1, g_wqq1); cudaGetSymbolAddress((void**)&wqq2, g_wqq2);
    cudaGetSymbolAddress((void**)&wkq1, g_wkq1); cudaGetSymbolAddress((void**)&wkq2, g_wkq2);
    cudaGetSymbolAddress((void**)&wvq1, g_wvq1); cudaGetSymbolAddress((void**)&wvq2, g_wvq2);
    cudaGetSymbolAddress((void**)&woq1, g_woq1); cudaGetSymbolAddress((void**)&woq2, g_woq2);
    cudaGetSymbolAddress((void**)&aq1,  g_aq1);  cudaGetSymbolAddress((void**)&aq2,  g_aq2);
    cudaGetSymbolAddress((void**)&sx,  g_sx);  cudaGetSymbolAddress((void**)&sc,  g_sc);
    cudaGetSymbolAddress((void**)&swq, g_swq); cudaGetSymbolAddress((void**)&swk, g_swk);
    cudaGetSymbolAddress((void**)&swv, g_swv); cudaGetSymbolAddress((void**)&swo, g_swo);
    cudaGetSymbolAddress((void**)&sa,  g_sa);

    cudaFuncSetAttribute(gemm_i8, cudaFuncAttributeMaxDynamicSharedMemorySize, QSMEM);

    quant_rows<<<ROWS_X, 256>>>(x,     xq1,  xq2,  sx,  DIM_);
    quant_rows<<<ROWS_C, 256>>>(chars, cq1,  cq2,  sc,  DIM_);
    quant_rows<<<ROWS_W, 256>>>(wq,    wqq1, wqq2, swq, DIM_);
    quant_rows<<<ROWS_W, 256>>>(wk,    wkq1, wkq2, swk, DIM_);
    quant_rows<<<ROWS_W, 256>>>(wv,    wvq1, wvq2, swv, DIM_);
    quant_rows<<<DIM_,   256>>>(wo,    woq1, woq2, swo, BMM_);

    gemm_i8<<<dim3(BMM_ / QBN, T_ / QBM), 256, QSMEM>>>(
        xq1, xq2, sx, wqq1, wqq2, swq, q, T_, BMM_, DIM_);
    gemm_i8<<<dim3(BMM_ / QBN, (T_ * CV_) / QBM), 256, QSMEM>>>(
        cq1, cq2, sc, wkq1, wkq2, swk, k, T_ * CV_, BMM_, DIM_);
    gemm_i8<<<dim3(BMM_ / QBN, (T_ * CV_) / QBM), 256, QSMEM>>>(
        cq1, cq2, sc, wvq1, wvq2, swv, v, T_ * CV_, BMM_, DIM_);

    attn_kernel<<<dim3(T_, NH_ / 4), 256>>>(q, k, v, att);

    quant_rows<<<T_, 256>>>(att, aq1, aq2, sa, BMM_);
    gemm_i8<<<dim3(DIM_ / QBN, T_ / QBM), 256, QSMEM>>>(
        aq1, aq2, sa, woq1, woq2, swo, out, T_, DIM_, BMM_);
}

// round 7
// speedup vs baseline: 1.6978x; 1.6978x over previous
#include <cuda_runtime.h>
#include <cuda_bf16.h>
#include <cstdint>
#include <math.h>

typedef __nv_bfloat16 bf16;
#define T_ 1024
#define CV_ 8
#define DIM_ 2048
#define NH_ 32

__device__ float g_v[T_ * CV_ * DIM_];
__device__ __align__(16) bf16 g_xh[T_ * DIM_], g_xl[T_ * DIM_];
__device__ __align__(16) bf16 g_chh[T_ * CV_ * DIM_], g_chl[T_ * CV_ * DIM_];
__device__ __align__(16) bf16 g_wqh[DIM_ * DIM_], g_wql[DIM_ * DIM_];
__device__ __align__(16) bf16 g_wkth[DIM_ * DIM_], g_wktl[DIM_ * DIM_];
__device__ __align__(16) bf16 g_wvh[DIM_ * DIM_], g_wvl[DIM_ * DIM_];
__device__ __align__(16) bf16 g_woh[DIM_ * DIM_], g_wol[DIM_ * DIM_];
__device__ __align__(16) bf16 g_qh[T_ * DIM_], g_ql[T_ * DIM_];
__device__ __align__(16) bf16 g_qkh[(size_t)NH_ * T_ * DIM_], g_qkl[(size_t)NH_ * T_ * DIM_];
__device__ __align__(16) bf16 g_ah[T_ * DIM_], g_al[T_ * DIM_];

__device__ __forceinline__ uint32_t smem_u32(const void* p) {
    uint32_t a;
    asm("{ .reg .u64 t; cvta.to.shared.u64 t, %1; cvt.u32.u64 %0, t; }" : "=r"(a) : "l"(p));
    return a;
}
__device__ __forceinline__ uint32_t swz64(uint32_t o) { return o ^ ((o >> 3) & 0x30); }
__device__ __forceinline__ void ldsm4(uint32_t& r0, uint32_t& r1, uint32_t& r2,
                                      uint32_t& r3, uint32_t a) {
    asm volatile("ldmatrix.sync.aligned.m8n8.x4.shared.b16 {%0,%1,%2,%3}, [%4];"
                 : "=r"(r0), "=r"(r1), "=r"(r2), "=r"(r3) : "r"(a));
}
__device__ __forceinline__ void mma16816(float* c, const uint32_t* a, const uint32_t* b) {
    asm volatile("mma.sync.aligned.m16n8k16.row.col.f32.bf16.bf16.f32 "
                 "{%0,%1,%2,%3}, {%4,%5,%6,%7}, {%8,%9}, {%0,%1,%2,%3};"
                 : "+f"(c[0]), "+f"(c[1]), "+f"(c[2]), "+f"(c[3])
                 : "r"(a[0]), "r"(a[1]), "r"(a[2]), "r"(a[3]), "r"(b[0]), "r"(b[1]));
}
__device__ __forceinline__ void cp16(uint32_t s, const void* g) {
    asm volatile("cp.async.cg.shared.global [%0], [%1], 16;" :: "r"(s), "l"(g) : "memory");
}
__device__ __forceinline__ void cp16z(uint32_t s, const void* g, int sz) {
    asm volatile("cp.async.cg.shared.global [%0], [%1], 16, %2;" :: "r"(s), "l"(g), "r"(sz) : "memory");
}
__device__ __forceinline__ void cp_commit() { asm volatile("cp.async.commit_group;" ::: "memory"); }
template <int N> __device__ __forceinline__ void cp_wait() {
    asm volatile("cp.async.wait_group %0;" :: "n"(N) : "memory");
}
__device__ __forceinline__ uint32_t pack_hi2(float x, float y, float& lx, float& ly) {
    bf16 hx = __float2bfloat16_rn(x), hy = __float2bfloat16_rn(y);
    lx = x - __bfloat162float(hx); ly = y - __bfloat162float(hy);
    __nv_bfloat162 h; h.x = hx; h.y = hy;
    return *reinterpret_cast<uint32_t*>(&h);
}
__device__ __forceinline__ uint32_t pack2(float x, float y) {
    __nv_bfloat162 h; h.x = __float2bfloat16_rn(x); h.y = __float2bfloat16_rn(y);
    return *reinterpret_cast<uint32_t*>(&h);
}

__global__ void __launch_bounds__(256)
cvt_split(const float4* __restrict__ src, uint2* __restrict__ h, uint2* __restrict__ l, int n4) {
    for (int i = blockIdx.x * blockDim.x + threadIdx.x; i < n4; i += gridDim.x * blockDim.x) {
        float4 f = src[i];
        float lx, ly, lz, lw;
        uint32_t h0 = pack_hi2(f.x, f.y, lx, ly);
        uint32_t h1 = pack_hi2(f.z, f.w, lz, lw);
        h[i] = make_uint2(h0, h1);
        l[i] = make_uint2(pack2(lx, ly), pack2(lz, lw));
    }
}

// wkT[c][d] = wk[d][c], split to bf16 hi/lo
__global__ void __launch_bounds__(256)
transpose_split(const float* __restrict__ src, bf16* __restrict__ th, bf16* __restrict__ tl) {
    __shared__ float ts[32][33];
    const int bx = blockIdx.x * 32, by = blockIdx.y * 32;
    const int x = threadIdx.x & 31, y0 = threadIdx.x >> 5;
#pragma unroll
    for (int i = 0; i < 4; i++)
        ts[y0 + i * 8][x] = src[(size_t)(by + y0 + i * 8) * DIM_ + bx + x];
    __syncthreads();
#pragma unroll
    for (int i = 0; i < 4; i++) {
        const int c = bx + y0 + i * 8;
        const float v = ts[x][y0 + i * 8];
        bf16 hh = __float2bfloat16_rn(v);
        th[(size_t)c * DIM_ + by + x] = hh;
        tl[(size_t)c * DIM_ + by + x] = __float2bfloat16_rn(v - __bfloat162float(hh));
    }
}

// ---- generic bf16x3 GEMM: C = A*B^T, 128x256x32 tile, 3-stage cp.async ----
#define BM 128
#define BN 256
#define AH_OFF 0
#define AL_OFF 8192
#define BH_OFF 16384
#define BL_OFF 32768
#define STAGE 49152
#define GEMM_SMEM (3 * STAGE)

__device__ __forceinline__ void load_stage_g(
    const bf16* Ah, const bf16* Al, const bf16* Bh, const bf16* Bl,
    int bm, int bn, int lda, int ldb, int kc, uint32_t stg, int tid) {
#pragma unroll
    for (int j = 0; j < 2; j++) {
        const int idx = j * 256 + tid, r = idx >> 2, c = idx & 3;
        const uint32_t so = swz64((uint32_t)(r * 64 + c * 16));
        const size_t ga = (size_t)(bm + r) * lda + kc + c * 8;
        cp16(stg + AH_OFF + so, Ah + ga);
        cp16(stg + AL_OFF + so, Al + ga);
    }
#pragma unroll
    for (int j = 0; j < 4; j++) {
        const int idx = j * 256 + tid, r = idx >> 2, c = idx & 3;
        const uint32_t so = swz64((uint32_t)(r * 64 + c * 16));
        const size_t gb = (size_t)(bn + r) * ldb + kc + c * 8;
        cp16(stg + BH_OFF + so, Bh + gb);
        cp16(stg + BL_OFF + so, Bl + gb);
    }
}

template <int SPLIT>
__global__ void __launch_bounds__(256, 1)
gemm_g(const bf16* __restrict__ Ah, const bf16* __restrict__ Al, int lda, int aZ,
       const bf16* __restrict__ Bh, const bf16* __restrict__ Bl, int ldb, int bZ,
       float* __restrict__ C, bf16* __restrict__ Ch, bf16* __restrict__ Cl,
       int ldc, size_t cZ, int K) {
    extern __shared__ char sm[];
    const uint32_t sb = smem_u32(sm);
    const int tid = threadIdx.x, lane = tid & 31, wid = tid >> 5;
    const int wm = wid >> 2, wn = wid & 3;
    const int bm = blockIdx.y * BM, bn = blockIdx.x * BN, z = blockIdx.z;
    Ah += (size_t)z * aZ; Al += (size_t)z * aZ;
    Bh += (size_t)z * bZ; Bl += (size_t)z * bZ;

    float acc[4][8][4];
#pragma unroll
    for (int i = 0; i < 4; i++)
#pragma unroll
        for (int j = 0; j < 8; j++)
#pragma unroll
            for (int r = 0; r < 4; r++) acc[i][j][r] = 0.f;

    const int NCHK = K / 32;
    load_stage_g(Ah, Al, Bh, Bl, bm, bn, lda, ldb, 0, sb, tid); cp_commit();
    load_stage_g(Ah, Al, Bh, Bl, bm, bn, lda, ldb, 32, sb + STAGE, tid); cp_commit();

    const int lr = (lane & 7) + ((lane >> 3) & 1) * 8, lc16 = lane >> 4;

    for (int c = 0; c < NCHK; c++) {
        cp_wait<1>();
        __syncthreads();
        if (c + 2 < NCHK)
            load_stage_g(Ah, Al, Bh, Bl, bm, bn, lda, ldb, (c + 2) * 32,
                         sb + (uint32_t)((c + 2) % 3) * STAGE, tid);
        cp_commit();
        const uint32_t stg = sb + (uint32_t)(c % 3) * STAGE;
#pragma unroll
        for (int ks = 0; ks < 2; ks++) {
            uint32_t ah[4][4], al[4][4];
#pragma unroll
            for (int mi = 0; mi < 4; mi++) {
                const int r = wm * 64 + mi * 16 + lr;
                const uint32_t so = swz64((uint32_t)(r * 64 + (ks * 2 + lc16) * 16));
                ldsm4(ah[mi][0], ah[mi][1], ah[mi][2], ah[mi][3], stg + AH_OFF + so);
                ldsm4(al[mi][0], al[mi][1], al[mi][2], al[mi][3], stg + AL_OFF + so);
            }
#pragma unroll
            for (int nj = 0; nj < 4; nj++) {
                const int r = wn * 64 + nj * 16 + lr;
                const uint32_t so = swz64((uint32_t)(r * 64 + (ks * 2 + lc16) * 16));
                uint32_t h0, h1, h2, h3, l0, l1, l2, l3;
                ldsm4(h0, h1, h2, h3, stg + BH_OFF + so);
                ldsm4(l0, l1, l2, l3, stg + BL_OFF + so);
                uint32_t b0h[2] = {h0, h2}, b1h[2] = {h1, h3};
                uint32_t b0l[2] = {l0, l2}, b1l[2] = {l1, l3};
#pragma unroll
                for (int mi = 0; mi < 4; mi++) {
                    mma16816(acc[mi][nj * 2], ah[mi], b0h);
                    mma16816(acc[mi][nj * 2], ah[mi], b0l);
                    mma16816(acc[mi][nj * 2], al[mi], b0h);
                    mma16816(acc[mi][nj * 2 + 1], ah[mi], b1h);
                    mma16816(acc[mi][nj * 2 + 1], ah[mi], b1l);
                    mma16816(acc[mi][nj * 2 + 1], al[mi], b1h);
                }
            }
        }
    }

    const int gr = lane >> 2, gc = (lane & 3) << 1;
#pragma unroll
    for (int mi = 0; mi < 4; mi++)
#pragma unroll
        for (int nn = 0; nn < 8; nn++) {
            const int row = bm + wm * 64 + mi * 16 + gr;
            const int col = bn + wn * 64 + nn * 8 + gc;
            if (SPLIT == 0) {
                *(float2*)(C + (size_t)row * ldc + col) =
                    make_float2(acc[mi][nn][0], acc[mi][nn][1]);
                *(float2*)(C + (size_t)(row + 8) * ldc + col) =
                    make_float2(acc[mi][nn][2], acc[mi][nn][3]);
            } else {
                const size_t i0 = (size_t)blockIdx.z * cZ + (size_t)row * ldc + col;
                const size_t i1 = i0 + (size_t)8 * ldc;
                float l0, l1, l2, l3;
                uint32_t h01 = pack_hi2(acc[mi][nn][0], acc[mi][nn][1], l0, l1);
                uint32_t h23 = pack_hi2(acc[mi][nn][2], acc[mi][nn][3], l2, l3);
                *(uint32_t*)(Ch + i0) = h01; *(uint32_t*)(Cl + i0) = pack2(l0, l1);
                *(uint32_t*)(Ch + i1) = h23; *(uint32_t*)(Cl + i1) = pack2(l2, l3);
            }
        }
}

// ---- fused attention, one CTA per t ----
// scores[h][j] = qk[h,t,:2048] . chars[(t-7)*8+j]; p<0 rows zero-filled ->
// score exactly 0 (matches reference zero-padded swa + softmax over 0s).
// RoPE drops out (q,k share the per-t rotation; v unrotated).
#define F_AH 0
#define F_AL 2048
#define F_BH 4096
#define F_BL 8192
#define F_STG 12288
#define F_S (3 * F_STG)
#define F_ATT (F_S + 32 * 66 * 4)
#define F_TOT (F_ATT + 32 * 64 * 4)

__device__ __forceinline__ void attn_load(const bf16* qsrc, size_t abase,
                                          const bf16* csrc, int t, int kc, uint32_t stg,
                                          uint32_t adst, uint32_t bdst, int r8, int c4) {
    cp16(stg + adst + swz64((uint32_t)(r8 * 64 + c4 * 16)), qsrc + abase + kc);
#pragma unroll
    for (int it = 0; it < 2; it++) {
        const int rr = it * 32 + r8;
        const int p = (t - 7) * 8 + rr;
        const int sz = (p >= 0) ? 16 : 0;
        const bf16* sp = csrc + (size_t)(p >= 0 ? p : 0) * DIM_ + kc + c4 * 8;
        cp16z(stg + bdst + swz64((uint32_t)(rr * 64 + c4 * 16)), sp, sz);
    }
    cp_commit();
}

__global__ void __launch_bounds__(256, 1)
attn_fused(const bf16* __restrict__ qkh, const bf16* __restrict__ qkl,
           const bf16* __restrict__ chh, const bf16* __restrict__ chl,
           const float* __restrict__ v, bf16* __restrict__ oh, bf16* __restrict__ ol) {
    extern __shared__ char sm[];
    const uint32_t sb = smem_u32(sm);
    const int t = blockIdx.x, tid = threadIdx.x;
    const int lane = tid & 31, wid = tid >> 5;
    const int mh = wid & 1, nq = wid >> 1;
    float* Ssm = (float*)(sm + F_S);
    float* Att = (float*)(sm + F_ATT);

    const int r8 = tid >> 3, q8 = tid & 7, c4 = q8 & 3;
    const bf16* qsrc = (q8 < 4) ? qkh : qkl;
    const bf16* csrc = (q8 < 4) ? chh : chl;
    const uint32_t adst = (q8 < 4) ? F_AH : F_AL;
    const uint32_t bdst = (q8 < 4) ? F_BH : F_BL;
    const size_t abase = ((size_t)r8 * T_ + t) * DIM_ + c4 * 8;

    attn_load(qsrc, abase, csrc, t, 0, sb, adst, bdst, r8, c4);
    attn_load(qsrc, abase, csrc, t, 32, sb + F_STG, adst, bdst, r8, c4);

    float acc0[4] = {0, 0, 0, 0}, acc1[4] = {0, 0, 0, 0};
    const int lr = (lane & 7) + ((lane >> 3) & 1) * 8, lc16 = lane >> 4;

    for (int c = 0; c < 64; c++) {
        cp_wait<1>();
        __syncthreads();
        if (c + 2 < 64)
            attn_load(qsrc, abase, csrc, t, (c + 2) * 32,
                      sb + (uint32_t)((c + 2) % 3) * F_STG, adst, bdst, r8, c4);
        else
            cp_commit();
        const uint32_t stg = sb + (uint32_t)(c % 3) * F_STG;
#pragma unroll
        for (int ks = 0; ks < 2; ks++) {
            uint32_t ah[4], al[4];
            const uint32_t soA = swz64((uint32_t)((mh * 16 + lr) * 64 + (ks * 2 + lc16) * 16));
            ldsm4(ah[0], ah[1], ah[2], ah[3], stg + F_AH + soA);
            ldsm4(al[0], al[1], al[2], al[3], stg + F_AL + soA);
            const uint32_t soB = swz64((uint32_t)((nq * 16 + lr) * 64 + (ks * 2 + lc16) * 16));
            uint32_t h0, h1, h2, h3, l0, l1, l2, l3;
            ldsm4(h0, h1, h2, h3, stg + F_BH + soB);
            ldsm4(l0, l1, l2, l3, stg + F_BL + soB);
            uint32_t b0h[2] = {h0, h2}, b1h[2] = {h1, h3};
            uint32_t b0l[2] = {l0, l2}, b1l[2] = {l1, l3};
            mma16816(acc0, ah, b0h); mma16816(acc0, ah, b0l); mma16816(acc0, al, b0h);
            mma16816(acc1, ah, b1h); mma16816(acc1, ah, b1l); mma16816(acc1, al, b1h);
        }
    }
    {
        const int gr = lane >> 2, gc = (lane & 3) << 1;
        const int row = mh * 16 + gr;
        const int c0 = nq * 16 + gc, c1 = nq * 16 + 8 + gc;
        Ssm[row * 66 + c0] = acc0[0] * 0.125f;
        Ssm[row * 66 + c0 + 1] = acc0[1] * 0.125f;
        Ssm[(row + 8) * 66 + c0] = acc0[2] * 0.125f;
        Ssm[(row + 8) * 66 + c0 + 1] = acc0[3] * 0.125f;
        Ssm[row * 66 + c1] = acc1[0] * 0.125f;
        Ssm[row * 66 + c1 + 1] = acc1[1] * 0.125f;
        Ssm[(row + 8) * 66 + c1] = acc1[2] * 0.125f;
        Ssm[(row + 8) * 66 + c1 + 1] = acc1[3] * 0.125f;
    }
    __syncthreads();
    {
        const int r = tid >> 3, l8 = tid & 7;
        float vals[8], m = -1e30f;
#pragma unroll
        for (int i = 0; i < 8; i++) {
            vals[i] = Ssm[r * 66 + l8 + i * 8];
            m = fmaxf(m, vals[i]);
        }
#pragma unroll
        for (int o = 4; o; o >>= 1) m = fmaxf(m, __shfl_xor_sync(0xffffffffu, m, o));
        float s = 0.f;
#pragma unroll
        for (int i = 0; i < 8; i++) { vals[i] = expf(vals[i] - m); s += vals[i]; }
#pragma unroll
        for (int o = 4; o; o >>= 1) s += __shfl_xor_sync(0xffffffffu, s, o);
        const float inv = 1.f / s;
#pragma unroll
        for (int i = 0; i < 8; i++) Att[r * 64 + l8 + i * 8] = vals[i] * inv;
    }
    __syncthreads();
    {
        const int h = tid >> 3, db = (tid & 7) * 8;
        float a8[8] = {0, 0, 0, 0, 0, 0, 0, 0};
        const int jlo = (t >= 7) ? 0 : (7 - t) * 8;
#pragma unroll 4
        for (int j = jlo; j < 64; j++) {
            const float w = Att[h * 64 + j];
            const int p = (t - 7) * 8 + j;
            const float4* vr = (const float4*)(v + (size_t)p * DIM_ + h * 64 + db);
            float4 v0 = vr[0], v1 = vr[1];
            a8[0] = fmaf(w, v0.x, a8[0]); a8[1] = fmaf(w, v0.y, a8[1]);
            a8[2] = fmaf(w, v0.z, a8[2]); a8[3] = fmaf(w, v0.w, a8[3]);
            a8[4] = fmaf(w, v1.x, a8[4]); a8[5] = fmaf(w, v1.y, a8[5]);
            a8[6] = fmaf(w, v1.z, a8[6]); a8[7] = fmaf(w, v1.w, a8[7]);
        }
        const size_t o = (size_t)t * DIM_ + h * 64 + db;
#pragma unroll
        for (int i = 0; i < 4; i++) {
            float l0, l1;
            uint32_t hh = pack_hi2(a8[i * 2], a8[i * 2 + 1], l0, l1);
            *(uint32_t*)(oh + o + i * 2) = hh;
            *(uint32_t*)(ol + o + i * 2) = pack2(l0, l1);
        }
    }
}

extern "C" void kernel_launch(void* const* d_in, const int* in_sizes, int n_in,
                              void* d_out, int out_size) {
    const float* x = (const float*)d_in[0];
    const float* chars = (const float*)d_in[1];
    const float* wq = (const float*)d_in[2];
    const float* wk = (const float*)d_in[3];
    const float* wv = (const float*)d_in[4];
    const float* wo = (const float*)d_in[5];
    float* out = (float*)d_out;

    float* v;
    bf16 *xh, *xl, *chh, *chl, *wqh, *wql, *wkth, *wktl, *wvh, *wvl, *woh, *wol;
    bf16 *qh, *ql, *qkh, *qkl, *ah, *al;
    cudaGetSymbolAddress((void**)&v, g_v);
    cudaGetSymbolAddress((void**)&xh, g_xh);    cudaGetSymbolAddress((void**)&xl, g_xl);
    cudaGetSymbolAddress((void**)&chh, g_chh);  cudaGetSymbolAddress((void**)&chl, g_chl);
    cudaGetSymbolAddress((void**)&wqh, g_wqh);  cudaGetSymbolAddress((void**)&wql, g_wql);
    cudaGetSymbolAddress((void**)&wkth, g_wkth); cudaGetSymbolAddress((void**)&wktl, g_wktl);
    cudaGetSymbolAddress((void**)&wvh, g_wvh);  cudaGetSymbolAddress((void**)&wvl, g_wvl);
    cudaGetSymbolAddress((void**)&woh, g_woh);  cudaGetSymbolAddress((void**)&wol, g_wol);
    cudaGetSymbolAddress((void**)&qh, g_qh);    cudaGetSymbolAddress((void**)&ql, g_ql);
    cudaGetSymbolAddress((void**)&qkh, g_qkh);  cudaGetSymbolAddress((void**)&qkl, g_qkl);
    cudaGetSymbolAddress((void**)&ah, g_ah);    cudaGetSymbolAddress((void**)&al, g_al);

    cudaFuncSetAttribute(gemm_g<0>, cudaFuncAttributeMaxDynamicSharedMemorySize, GEMM_SMEM);
    cudaFuncSetAttribute(gemm_g<1>, cudaFuncAttributeMaxDynamicSharedMemorySize, GEMM_SMEM);
    cudaFuncSetAttribute(attn_fused, cudaFuncAttributeMaxDynamicSharedMemorySize, F_TOT);

    auto cvt = [](const float* s, bf16* h, bf16* l, int n) {
        cvt_split<<<(n / 4 + 255) / 256, 256>>>((const float4*)s, (uint2*)h, (uint2*)l, n / 4);
    };
    cvt(x, xh, xl, T_ * DIM_);
    cvt(chars, chh, chl, T_ * CV_ * DIM_);
    cvt(wq, wqh, wql, DIM_ * DIM_);
    cvt(wv, wvh, wvl, DIM_ * DIM_);
    cvt(wo, woh, wol, DIM_ * DIM_);
    transpose_split<<<dim3(64, 64), 256>>>(wk, wkth, wktl);

    // q = x @ wq^T  (bf16 hi/lo out)
    gemm_g<1><<<dim3(DIM_ / BN, T_ / BM), 256, GEMM_SMEM>>>(
        xh, xl, DIM_, 0, wqh, wql, DIM_, 0, nullptr, qh, ql, DIM_, 0, DIM_);
    // qk[h] = q_h (1024x64) @ wkT_h^T  (z = 32 heads, K = 64)
    gemm_g<1><<<dim3(DIM_ / BN, T_ / BM, NH_), 256, GEMM_SMEM>>>(
        qh, ql, DIM_, 64, wkth, wktl, DIM_, 64, nullptr, qkh, qkl,
        DIM_, (size_t)T_ * DIM_, 64);
    // v = chars @ wv^T  (fp32 out)
    gemm_g<0><<<dim3(DIM_ / BN, (T_ * CV_) / BM), 256, GEMM_SMEM>>>(
        chh, chl, DIM_, 0, wvh, wvl, DIM_, 0, v, nullptr, nullptr, DIM_, 0, DIM_);

    attn_fused<<<T_, 256, F_TOT>>>(qkh, qkl, chh, chl, v, ah, al);

    // out = att @ wo^T
    gemm_g<0><<<dim3(DIM_ / BN, T_ / BM), 256, GEMM_SMEM>>>(
        ah, al, DIM_, 0, woh, wol, DIM_, 0, out, nullptr, nullptr, DIM_, 0, DIM_);
}

// round 8
// speedup vs baseline: 2.0353x; 1.1988x over previous
#include <cuda_runtime.h>
#include <cuda_bf16.h>
#include <cstdint>
#include <math.h>

typedef __nv_bfloat16 bf16;
#define T_ 1024
#define DIM_ 2048
#define NH_ 32

__device__ float g_q[T_ * DIM_];
__device__ float g_k[T_ * 8 * DIM_];
__device__ __align__(16) bf16 g_xh[T_ * DIM_], g_xl[T_ * DIM_];
__device__ __align__(16) bf16 g_chh[T_ * 8 * DIM_], g_chl[T_ * 8 * DIM_];
__device__ __align__(16) bf16 g_wqh[DIM_ * DIM_], g_wql[DIM_ * DIM_];
__device__ __align__(16) bf16 g_wkh[DIM_ * DIM_], g_wkl[DIM_ * DIM_];
__device__ __align__(16) bf16 g_wvh[DIM_ * DIM_], g_wvl[DIM_ * DIM_];
__device__ __align__(16) bf16 g_woh[DIM_ * DIM_], g_wol[DIM_ * DIM_];
__device__ __align__(16) bf16 g_mxh[(size_t)NH_ * T_ * DIM_], g_mxl[(size_t)NH_ * T_ * DIM_];
__device__ __align__(16) bf16 g_ath[T_ * DIM_], g_atl[T_ * DIM_];

__device__ __forceinline__ uint32_t smem_u32(const void* p) {
    uint32_t a;
    asm("{ .reg .u64 t; cvta.to.shared.u64 t, %1; cvt.u32.u64 %0, t; }" : "=r"(a) : "l"(p));
    return a;
}
__device__ __forceinline__ uint32_t swz64(uint32_t o) { return o ^ ((o >> 3) & 0x30); }
__device__ __forceinline__ void ldsm4(uint32_t& r0, uint32_t& r1, uint32_t& r2,
                                      uint32_t& r3, uint32_t a) {
    asm volatile("ldmatrix.sync.aligned.m8n8.x4.shared.b16 {%0,%1,%2,%3}, [%4];"
                 : "=r"(r0), "=r"(r1), "=r"(r2), "=r"(r3) : "r"(a));
}
__device__ __forceinline__ void mma16816(float* c, const uint32_t* a, const uint32_t* b) {
    asm volatile("mma.sync.aligned.m16n8k16.row.col.f32.bf16.bf16.f32 "
                 "{%0,%1,%2,%3}, {%4,%5,%6,%7}, {%8,%9}, {%0,%1,%2,%3};"
                 : "+f"(c[0]), "+f"(c[1]), "+f"(c[2]), "+f"(c[3])
                 : "r"(a[0]), "r"(a[1]), "r"(a[2]), "r"(a[3]), "r"(b[0]), "r"(b[1]));
}
__device__ __forceinline__ void cp16(uint32_t s, const void* g) {
    asm volatile("cp.async.cg.shared.global [%0], [%1], 16;" :: "r"(s), "l"(g) : "memory");
}
__device__ __forceinline__ void cp_commit() { asm volatile("cp.async.commit_group;" ::: "memory"); }
template <int N> __device__ __forceinline__ void cp_wait() {
    asm volatile("cp.async.wait_group %0;" :: "n"(N) : "memory");
}
__device__ __forceinline__ uint32_t pack_hi2(float x, float y, float& lx, float& ly) {
    bf16 hx = __float2bfloat16_rn(x), hy = __float2bfloat16_rn(y);
    lx = x - __bfloat162float(hx); ly = y - __bfloat162float(hy);
    __nv_bfloat162 h; h.x = hx; h.y = hy;
    return *reinterpret_cast<uint32_t*>(&h);
}
__device__ __forceinline__ uint32_t pack2(float x, float y) {
    __nv_bfloat162 h; h.x = __float2bfloat16_rn(x); h.y = __float2bfloat16_rn(y);
    return *reinterpret_cast<uint32_t*>(&h);
}

__global__ void __launch_bounds__(256)
cvt_split(const float4* __restrict__ src, uint2* __restrict__ h, uint2* __restrict__ l, int n4) {
    for (int i = blockIdx.x * blockDim.x + threadIdx.x; i < n4; i += gridDim.x * blockDim.x) {
        float4 f = src[i];
        float lx, ly, lz, lw;
        uint32_t h0 = pack_hi2(f.x, f.y, lx, ly);
        uint32_t h1 = pack_hi2(f.z, f.w, lz, lw);
        h[i] = make_uint2(h0, h1);
        l[i] = make_uint2(pack2(lx, ly), pack2(lz, lw));
    }
}

// ---- bf16x3 GEMM: C[M,2048] = A[M,2048]*B[2048,2048]^T, fp32 out ----
#define AH_OFF 0
#define AL_OFF 8192
#define BH_OFF 16384
#define BL_OFF 32768
#define STAGE 49152
#define GEMM_SMEM (3 * STAGE)

__device__ __forceinline__ void load_stage(const bf16* Ah, const bf16* Al,
                                           const bf16* Bh, const bf16* Bl,
                                           int bm, int bn, int kc, uint32_t stg, int tid) {
#pragma unroll
    for (int j = 0; j < 2; j++) {
        const int idx = j * 256 + tid, r = idx >> 2, c = idx & 3;
        const uint32_t so = swz64((uint32_t)(r * 64 + c * 16));
        const size_t ga = (size_t)(bm + r) * 2048 + kc + c * 8;
        cp16(stg + AH_OFF + so, Ah + ga);
        cp16(stg + AL_OFF + so, Al + ga);
    }
#pragma unroll
    for (int j = 0; j < 4; j++) {
        const int idx = j * 256 + tid, r = idx >> 2, c = idx & 3;
        const uint32_t so = swz64((uint32_t)(r * 64 + c * 16));
        const size_t gb = (size_t)(bn + r) * 2048 + kc + c * 8;
        cp16(stg + BH_OFF + so, Bh + gb);
        cp16(stg + BL_OFF + so, Bl + gb);
    }
}

__global__ void __launch_bounds__(256, 1)
gemm_bt(const bf16* __restrict__ Ah, const bf16* __restrict__ Al,
        const bf16* __restrict__ Bh, const bf16* __restrict__ Bl, float* __restrict__ C) {
    extern __shared__ char sm[];
    const uint32_t sb = smem_u32(sm);
    const int tid = threadIdx.x, lane = tid & 31, wid = tid >> 5;
    const int wm = wid >> 2, wn = wid & 3;
    const int bm = blockIdx.y * 128, bn = blockIdx.x * 256;

    float acc[4][8][4];
#pragma unroll
    for (int i = 0; i < 4; i++)
#pragma unroll
        for (int j = 0; j < 8; j++)
#pragma unroll
            for (int r = 0; r < 4; r++) acc[i][j][r] = 0.f;

    load_stage(Ah, Al, Bh, Bl, bm, bn, 0, sb, tid); cp_commit();
    load_stage(Ah, Al, Bh, Bl, bm, bn, 32, sb + STAGE, tid); cp_commit();
    const int lr = (lane & 7) + ((lane >> 3) & 1) * 8, lc16 = lane >> 4;

    for (int c = 0; c < 64; c++) {
        cp_wait<1>();
        __syncthreads();
        if (c + 2 < 64)
            load_stage(Ah, Al, Bh, Bl, bm, bn, (c + 2) * 32,
                       sb + (uint32_t)((c + 2) % 3) * STAGE, tid);
        cp_commit();
        const uint32_t stg = sb + (uint32_t)(c % 3) * STAGE;
#pragma unroll
        for (int ks = 0; ks < 2; ks++) {
            uint32_t ah[4][4], al[4][4];
#pragma unroll
            for (int mi = 0; mi < 4; mi++) {
                const int r = wm * 64 + mi * 16 + lr;
                const uint32_t so = swz64((uint32_t)(r * 64 + (ks * 2 + lc16) * 16));
                ldsm4(ah[mi][0], ah[mi][1], ah[mi][2], ah[mi][3], stg + AH_OFF + so);
                ldsm4(al[mi][0], al[mi][1], al[mi][2], al[mi][3], stg + AL_OFF + so);
            }
#pragma unroll
            for (int nj = 0; nj < 4; nj++) {
                const int r = wn * 64 + nj * 16 + lr;
                const uint32_t so = swz64((uint32_t)(r * 64 + (ks * 2 + lc16) * 16));
                uint32_t h0, h1, h2, h3, l0, l1, l2, l3;
                ldsm4(h0, h1, h2, h3, stg + BH_OFF + so);
                ldsm4(l0, l1, l2, l3, stg + BL_OFF + so);
                uint32_t b0h[2] = {h0, h2}, b1h[2] = {h1, h3};
                uint32_t b0l[2] = {l0, l2}, b1l[2] = {l1, l3};
#pragma unroll
                for (int mi = 0; mi < 4; mi++) {
                    mma16816(acc[mi][nj * 2], ah[mi], b0h);
                    mma16816(acc[mi][nj * 2], ah[mi], b0l);
                    mma16816(acc[mi][nj * 2], al[mi], b0h);
                    mma16816(acc[mi][nj * 2 + 1], ah[mi], b1h);
                    mma16816(acc[mi][nj * 2 + 1], ah[mi], b1l);
                    mma16816(acc[mi][nj * 2 + 1], al[mi], b1h);
                }
            }
        }
    }
    const int gr = lane >> 2, gc = (lane & 3) << 1;
#pragma unroll
    for (int mi = 0; mi < 4; mi++)
#pragma unroll
        for (int nn = 0; nn < 8; nn++) {
            const int row = bm + wm * 64 + mi * 16 + gr;
            const int col = bn + wn * 64 + nn * 8 + gc;
            *(float2*)(C + (size_t)row * 2048 + col) = make_float2(acc[mi][nn][0], acc[mi][nn][1]);
            *(float2*)(C + (size_t)(row + 8) * 2048 + col) = make_float2(acc[mi][nn][2], acc[mi][nn][3]);
        }
}

// ---- batched N=64 GEMM: att[t, z*64+n] = mixed[z] @ wv_z^T, bf16 hi/lo out ----
#define N64_AH 0
#define N64_AL 8192
#define N64_BH 16384
#define N64_BL 20480
#define N64_STG 24576
#define N64_SMEM (3 * N64_STG)

__device__ __forceinline__ void n64_load(const bf16* Ah, const bf16* Al,
                                         const bf16* Bh, const bf16* Bl,
                                         int bm, int kc, uint32_t stg, int tid) {
#pragma unroll
    for (int j = 0; j < 2; j++) {
        const int idx = j * 256 + tid, r = idx >> 2, c = idx & 3;
        const uint32_t so = swz64((uint32_t)(r * 64 + c * 16));
        const size_t ga = (size_t)(bm + r) * 2048 + kc + c * 8;
        cp16(stg + N64_AH + so, Ah + ga);
        cp16(stg + N64_AL + so, Al + ga);
    }
    {
        const int r = tid >> 2, c = tid & 3;
        const uint32_t so = swz64((uint32_t)(r * 64 + c * 16));
        const size_t gb = (size_t)r * 2048 + kc + c * 8;
        cp16(stg + N64_BH + so, Bh + gb);
        cp16(stg + N64_BL + so, Bl + gb);
    }
}

__global__ void __launch_bounds__(256, 1)
gemm_n64(const bf16* __restrict__ Ah0, const bf16* __restrict__ Al0,
         const bf16* __restrict__ Bh0, const bf16* __restrict__ Bl0,
         bf16* __restrict__ Ch, bf16* __restrict__ Cl) {
    extern __shared__ char sm[];
    const uint32_t sb = smem_u32(sm);
    const int tid = threadIdx.x, lane = tid & 31, wid = tid >> 5;
    const int wm = wid >> 1, wn = wid & 1;
    const int bm = blockIdx.x * 128, z = blockIdx.y;
    const bf16* Ah = Ah0 + (size_t)z * T_ * 2048;
    const bf16* Al = Al0 + (size_t)z * T_ * 2048;
    const bf16* Bh = Bh0 + (size_t)z * 64 * 2048;
    const bf16* Bl = Bl0 + (size_t)z * 64 * 2048;

    float acc[2][4][4];
#pragma unroll
    for (int i = 0; i < 2; i++)
#pragma unroll
        for (int j = 0; j < 4; j++)
#pragma unroll
            for (int r = 0; r < 4; r++) acc[i][j][r] = 0.f;

    n64_load(Ah, Al, Bh, Bl, bm, 0, sb, tid); cp_commit();
    n64_load(Ah, Al, Bh, Bl, bm, 32, sb + N64_STG, tid); cp_commit();
    const int lr = (lane & 7) + ((lane >> 3) & 1) * 8, lc16 = lane >> 4;

    for (int c = 0; c < 64; c++) {
        cp_wait<1>();
        __syncthreads();
        if (c + 2 < 64)
            n64_load(Ah, Al, Bh, Bl, bm, (c + 2) * 32,
                     sb + (uint32_t)((c + 2) % 3) * N64_STG, tid);
        cp_commit();
        const uint32_t stg = sb + (uint32_t)(c % 3) * N64_STG;
#pragma unroll
        for (int ks = 0; ks < 2; ks++) {
            uint32_t ah[2][4], al[2][4];
#pragma unroll
            for (int mi = 0; mi < 2; mi++) {
                const int r = wm * 32 + mi * 16 + lr;
                const uint32_t so = swz64((uint32_t)(r * 64 + (ks * 2 + lc16) * 16));
                ldsm4(ah[mi][0], ah[mi][1], ah[mi][2], ah[mi][3], stg + N64_AH + so);
                ldsm4(al[mi][0], al[mi][1], al[mi][2], al[mi][3], stg + N64_AL + so);
            }
#pragma unroll
            for (int nj = 0; nj < 2; nj++) {
                const int r = wn * 32 + nj * 16 + lr;
                const uint32_t so = swz64((uint32_t)(r * 64 + (ks * 2 + lc16) * 16));
                uint32_t h0, h1, h2, h3, l0, l1, l2, l3;
                ldsm4(h0, h1, h2, h3, stg + N64_BH + so);
                ldsm4(l0, l1, l2, l3, stg + N64_BL + so);
                uint32_t b0h[2] = {h0, h2}, b1h[2] = {h1, h3};
                uint32_t b0l[2] = {l0, l2}, b1l[2] = {l1, l3};
#pragma unroll
                for (int mi = 0; mi < 2; mi++) {
                    mma16816(acc[mi][nj * 2], ah[mi], b0h);
                    mma16816(acc[mi][nj * 2], ah[mi], b0l);
                    mma16816(acc[mi][nj * 2], al[mi], b0h);
                    mma16816(acc[mi][nj * 2 + 1], ah[mi], b1h);
                    mma16816(acc[mi][nj * 2 + 1], ah[mi], b1l);
                    mma16816(acc[mi][nj * 2 + 1], al[mi], b1h);
                }
            }
        }
    }
    const int gr = lane >> 2, gc = (lane & 3) << 1;
#pragma unroll
    for (int mi = 0; mi < 2; mi++)
#pragma unroll
        for (int nn = 0; nn < 4; nn++) {
            const int row = bm + wm * 32 + mi * 16 + gr;
            const int col = wn * 32 + nn * 8 + gc;
            const size_t i0 = (size_t)z * 64 + (size_t)row * 2048 + col;
            const size_t i1 = i0 + (size_t)8 * 2048;
            float l0, l1, l2, l3;
            uint32_t h01 = pack_hi2(acc[mi][nn][0], acc[mi][nn][1], l0, l1);
            uint32_t h23 = pack_hi2(acc[mi][nn][2], acc[mi][nn][3], l2, l3);
            *(uint32_t*)(Ch + i0) = h01; *(uint32_t*)(Cl + i0) = pack2(l0, l1);
            *(uint32_t*)(Ch + i1) = h23; *(uint32_t*)(Cl + i1) = pack2(l2, l3);
        }
}

// ---- attnmix: scores (fp32) + softmax + char-mixing, one CTA per t ----
// scores[h][j] = q[t,h]·k[(t-7)*8+j, h] / 8; j<jlo (padded) -> score 0.
// mixed[h][t][c] = sum_j at[h][j]*chars[(t-7)*8+j][c], split to bf16 hi/lo.
// RoPE drops out (q,k share the per-t rotation; chars/v unrotated in ref).
#define SCP 66
__global__ void __launch_bounds__(256)
attnmix(const float* __restrict__ q, const float* __restrict__ k,
        const float* __restrict__ chars, bf16* __restrict__ mh, bf16* __restrict__ ml) {
    const int t = blockIdx.x, tid = threadIdx.x;
    __shared__ float qsm[2048];
    __shared__ float sc[32 * SCP];
    __shared__ float at[32 * 64];
    ((float4*)qsm)[tid] = ((const float4*)(q + (size_t)t * 2048))[tid];
    ((float4*)qsm)[tid + 256] = ((const float4*)(q + (size_t)t * 2048))[tid + 256];
    __syncthreads();
    const int jlo = (t >= 7) ? 0 : (7 - t) * 8;
    {
        const int j = tid >> 2, hq = tid & 3;
        const float* kr = k + (size_t)((t - 7) * 8 + j) * 2048;
#pragma unroll
        for (int i = 0; i < 8; i++) {
            const int h = hq * 8 + i;
            float s = 0.f;
            if (j >= jlo) {
                const float4* k4 = (const float4*)(kr + h * 64);
                const float4* q4 = (const float4*)(qsm + h * 64);
#pragma unroll
                for (int d = 0; d < 16; d++) {
                    float4 a = q4[d], b = k4[d];
                    s = fmaf(a.x, b.x, s); s = fmaf(a.y, b.y, s);
                    s = fmaf(a.z, b.z, s); s = fmaf(a.w, b.w, s);
                }
                s *= 0.125f;
            }
            sc[h * SCP + j] = s;
        }
    }
    __syncthreads();
    {
        const int r = tid >> 3, l8 = tid & 7;
        float vals[8], m = -1e30f;
#pragma unroll
        for (int i = 0; i < 8; i++) { vals[i] = sc[r * SCP + l8 + i * 8]; m = fmaxf(m, vals[i]); }
#pragma unroll
        for (int o = 4; o; o >>= 1) m = fmaxf(m, __shfl_xor_sync(0xffffffffu, m, o));
        float s = 0.f;
#pragma unroll
        for (int i = 0; i < 8; i++) { vals[i] = expf(vals[i] - m); s += vals[i]; }
#pragma unroll
        for (int o = 4; o; o >>= 1) s += __shfl_xor_sync(0xffffffffu, s, o);
        const float inv = 1.f / s;
#pragma unroll
        for (int i = 0; i < 8; i++) at[r * 64 + l8 + i * 8] = vals[i] * inv;
    }
    __syncthreads();
    {
        const int hg = tid >> 5, cg = tid & 31;
        const float* cbase = chars + (size_t)((t - 7) * 8) * 2048;
        for (int cb = 0; cb < 8; cb++) {
            const int c0 = cb * 256 + cg * 8;
            float acc[4][8];
#pragma unroll
            for (int a = 0; a < 4; a++)
#pragma unroll
                for (int b = 0; b < 8; b++) acc[a][b] = 0.f;
            for (int j = jlo; j < 64; j++) {
                const float4* cw = (const float4*)(cbase + (size_t)j * 2048 + c0);
                float4 v0 = cw[0], v1 = cw[1];
#pragma unroll
                for (int hh = 0; hh < 4; hh++) {
                    const float w = at[(hg * 4 + hh) * 64 + j];
                    acc[hh][0] = fmaf(w, v0.x, acc[hh][0]); acc[hh][1] = fmaf(w, v0.y, acc[hh][1]);
                    acc[hh][2] = fmaf(w, v0.z, acc[hh][2]); acc[hh][3] = fmaf(w, v0.w, acc[hh][3]);
                    acc[hh][4] = fmaf(w, v1.x, acc[hh][4]); acc[hh][5] = fmaf(w, v1.y, acc[hh][5]);
                    acc[hh][6] = fmaf(w, v1.z, acc[hh][6]); acc[hh][7] = fmaf(w, v1.w, acc[hh][7]);
                }
            }
#pragma unroll
            for (int hh = 0; hh < 4; hh++) {
                const int h = hg * 4 + hh;
                const size_t o = ((size_t)h * T_ + t) * 2048 + c0;
                uint32_t hv[4], lv[4];
#pragma unroll
                for (int i = 0; i < 4; i++) {
                    float l0, l1;
                    hv[i] = pack_hi2(acc[hh][i * 2], acc[hh][i * 2 + 1], l0, l1);
                    lv[i] = pack2(l0, l1);
                }
                *(uint4*)(mh + o) = make_uint4(hv[0], hv[1], hv[2], hv[3]);
                *(uint4*)(ml + o) = make_uint4(lv[0], lv[1], lv[2], lv[3]);
            }
        }
    }
}

extern "C" void kernel_launch(void* const* d_in, const int* in_sizes, int n_in,
                              void* d_out, int out_size) {
    const float* x = (const float*)d_in[0];
    const float* chars = (const float*)d_in[1];
    const float* wq = (const float*)d_in[2];
    const float* wk = (const float*)d_in[3];
    const float* wv = (const float*)d_in[4];
    const float* wo = (const float*)d_in[5];
    float* out = (float*)d_out;

    float *q, *k;
    bf16 *xh, *xl, *chh, *chl, *wqh, *wql, *wkh, *wkl, *wvh, *wvl, *woh, *wol;
    bf16 *mxh, *mxl, *ath, *atl;
    cudaGetSymbolAddress((void**)&q, g_q);     cudaGetSymbolAddress((void**)&k, g_k);
    cudaGetSymbolAddress((void**)&xh, g_xh);   cudaGetSymbolAddress((void**)&xl, g_xl);
    cudaGetSymbolAddress((void**)&chh, g_chh); cudaGetSymbolAddress((void**)&chl, g_chl);
    cudaGetSymbolAddress((void**)&wqh, g_wqh); cudaGetSymbolAddress((void**)&wql, g_wql);
    cudaGetSymbolAddress((void**)&wkh, g_wkh); cudaGetSymbolAddress((void**)&wkl, g_wkl);
    cudaGetSymbolAddress((void**)&wvh, g_wvh); cudaGetSymbolAddress((void**)&wvl, g_wvl);
    cudaGetSymbolAddress((void**)&woh, g_woh); cudaGetSymbolAddress((void**)&wol, g_wol);
    cudaGetSymbolAddress((void**)&mxh, g_mxh); cudaGetSymbolAddress((void**)&mxl, g_mxl);
    cudaGetSymbolAddress((void**)&ath, g_ath); cudaGetSymbolAddress((void**)&atl, g_atl);

    cudaFuncSetAttribute(gemm_bt, cudaFuncAttributeMaxDynamicSharedMemorySize, GEMM_SMEM);
    cudaFuncSetAttribute(gemm_n64, cudaFuncAttributeMaxDynamicSharedMemorySize, N64_SMEM);

    auto cvt = [](const float* s, bf16* h, bf16* l, int n) {
        cvt_split<<<(n / 4 + 255) / 256, 256>>>((const float4*)s, (uint2*)h, (uint2*)l, n / 4);
    };
    cvt(x, xh, xl, T_ * DIM_);
    cvt(chars, chh, chl, T_ * 8 * DIM_);
    cvt(wq, wqh, wql, DIM_ * DIM_);
    cvt(wk, wkh, wkl, DIM_ * DIM_);
    cvt(wv, wvh, wvl, DIM_ * DIM_);
    cvt(wo, woh, wol, DIM_ * DIM_);

    gemm_bt<<<dim3(8, 8), 256, GEMM_SMEM>>>(xh, xl, wqh, wql, q);        // q
    gemm_bt<<<dim3(8, 64), 256, GEMM_SMEM>>>(chh, chl, wkh, wkl, k);     // k
    attnmix<<<T_, 256>>>(q, k, chars, mxh, mxl);                          // scores+softmax+mix
    gemm_n64<<<dim3(8, 32), 256, N64_SMEM>>>(mxh, mxl, wvh, wvl, ath, atl); // v-proj
    gemm_bt<<<dim3(8, 8), 256, GEMM_SMEM>>>(ath, atl, woh, wol, out);    // o-proj
}

// round 9
// speedup vs baseline: 2.6908x; 1.3221x over previous
#include <cuda_runtime.h>
#include <cuda_bf16.h>
#include <cuda_fp16.h>
#include <cstdint>
#include <math.h>

typedef __nv_bfloat16 bf16;
#define T_ 1024
#define DIM_ 2048
#define NH_ 32

__device__ float g_q[T_ * DIM_];
__device__ float g_k[T_ * 8 * DIM_];
__device__ __align__(16) bf16 g_xh[T_ * DIM_], g_xl[T_ * DIM_];
__device__ __align__(16) __half g_chf[T_ * 8 * DIM_];
__device__ __align__(16) __half g_wkf[DIM_ * DIM_];
__device__ __align__(16) bf16 g_wqh[DIM_ * DIM_], g_wql[DIM_ * DIM_];
__device__ __align__(16) bf16 g_wvh[DIM_ * DIM_], g_wvl[DIM_ * DIM_];
__device__ __align__(16) bf16 g_woh[DIM_ * DIM_], g_wol[DIM_ * DIM_];
__device__ __align__(16) bf16 g_mxh[(size_t)NH_ * T_ * DIM_], g_mxl[(size_t)NH_ * T_ * DIM_];
__device__ __align__(16) bf16 g_ath[T_ * DIM_], g_atl[T_ * DIM_];

__device__ __forceinline__ uint32_t smem_u32(const void* p) {
    uint32_t a;
    asm("{ .reg .u64 t; cvta.to.shared.u64 t, %1; cvt.u32.u64 %0, t; }" : "=r"(a) : "l"(p));
    return a;
}
__device__ __forceinline__ uint32_t swz64(uint32_t o) { return o ^ ((o >> 3) & 0x30); }
__device__ __forceinline__ void ldsm4(uint32_t& r0, uint32_t& r1, uint32_t& r2,
                                      uint32_t& r3, uint32_t a) {
    asm volatile("ldmatrix.sync.aligned.m8n8.x4.shared.b16 {%0,%1,%2,%3}, [%4];"
                 : "=r"(r0), "=r"(r1), "=r"(r2), "=r"(r3) : "r"(a));
}
__device__ __forceinline__ void mma16816(float* c, const uint32_t* a, const uint32_t* b) {
    asm volatile("mma.sync.aligned.m16n8k16.row.col.f32.bf16.bf16.f32 "
                 "{%0,%1,%2,%3}, {%4,%5,%6,%7}, {%8,%9}, {%0,%1,%2,%3};"
                 : "+f"(c[0]), "+f"(c[1]), "+f"(c[2]), "+f"(c[3])
                 : "r"(a[0]), "r"(a[1]), "r"(a[2]), "r"(a[3]), "r"(b[0]), "r"(b[1]));
}
__device__ __forceinline__ void mmaf16(float* c, const uint32_t* a, const uint32_t* b) {
    asm volatile("mma.sync.aligned.m16n8k16.row.col.f32.f16.f16.f32 "
                 "{%0,%1,%2,%3}, {%4,%5,%6,%7}, {%8,%9}, {%0,%1,%2,%3};"
                 : "+f"(c[0]), "+f"(c[1]), "+f"(c[2]), "+f"(c[3])
                 : "r"(a[0]), "r"(a[1]), "r"(a[2]), "r"(a[3]), "r"(b[0]), "r"(b[1]));
}
__device__ __forceinline__ void cp16(uint32_t s, const void* g) {
    asm volatile("cp.async.cg.shared.global [%0], [%1], 16;" :: "r"(s), "l"(g) : "memory");
}
__device__ __forceinline__ void cp_commit() { asm volatile("cp.async.commit_group;" ::: "memory"); }
template <int N> __device__ __forceinline__ void cp_wait() {
    asm volatile("cp.async.wait_group %0;" :: "n"(N) : "memory");
}
__device__ __forceinline__ uint32_t pack_hi2(float x, float y, float& lx, float& ly) {
    bf16 hx = __float2bfloat16_rn(x), hy = __float2bfloat16_rn(y);
    lx = x - __bfloat162float(hx); ly = y - __bfloat162float(hy);
    __nv_bfloat162 h; h.x = hx; h.y = hy;
    return *reinterpret_cast<uint32_t*>(&h);
}
__device__ __forceinline__ uint32_t pack2(float x, float y) {
    __nv_bfloat162 h; h.x = __float2bfloat16_rn(x); h.y = __float2bfloat16_rn(y);
    return *reinterpret_cast<uint32_t*>(&h);
}

__global__ void __launch_bounds__(256)
cvt_split(const float4* __restrict__ src, uint2* __restrict__ h, uint2* __restrict__ l, int n4) {
    for (int i = blockIdx.x * blockDim.x + threadIdx.x; i < n4; i += gridDim.x * blockDim.x) {
        float4 f = src[i];
        float lx, ly, lz, lw;
        uint32_t h0 = pack_hi2(f.x, f.y, lx, ly);
        uint32_t h1 = pack_hi2(f.z, f.w, lz, lw);
        h[i] = make_uint2(h0, h1);
        l[i] = make_uint2(pack2(lx, ly), pack2(lz, lw));
    }
}
__global__ void __launch_bounds__(256)
cvt_f16(const float4* __restrict__ src, uint2* __restrict__ d, int n4) {
    for (int i = blockIdx.x * blockDim.x + threadIdx.x; i < n4; i += gridDim.x * blockDim.x) {
        float4 f = src[i];
        __half2 a = __float22half2_rn(make_float2(f.x, f.y));
        __half2 b = __float22half2_rn(make_float2(f.z, f.w));
        d[i] = make_uint2(*(uint32_t*)&a, *(uint32_t*)&b);
    }
}

// ---- bf16x3 GEMM: C[M,2048] = A[M,2048]*B[2048,2048]^T, fp32 out ----
#define AH_OFF 0
#define AL_OFF 8192
#define BH_OFF 16384
#define BL_OFF 32768
#define STAGE 49152
#define GEMM_SMEM (3 * STAGE)

__device__ __forceinline__ void load_stage(const bf16* Ah, const bf16* Al,
                                           const bf16* Bh, const bf16* Bl,
                                           int bm, int bn, int kc, uint32_t stg, int tid) {
#pragma unroll
    for (int j = 0; j < 2; j++) {
        const int idx = j * 256 + tid, r = idx >> 2, c = idx & 3;
        const uint32_t so = swz64((uint32_t)(r * 64 + c * 16));
        const size_t ga = (size_t)(bm + r) * 2048 + kc + c * 8;
        cp16(stg + AH_OFF + so, Ah + ga);
        cp16(stg + AL_OFF + so, Al + ga);
    }
#pragma unroll
    for (int j = 0; j < 4; j++) {
        const int idx = j * 256 + tid, r = idx >> 2, c = idx & 3;
        const uint32_t so = swz64((uint32_t)(r * 64 + c * 16));
        const size_t gb = (size_t)(bn + r) * 2048 + kc + c * 8;
        cp16(stg + BH_OFF + so, Bh + gb);
        cp16(stg + BL_OFF + so, Bl + gb);
    }
}

__global__ void __launch_bounds__(256, 1)
gemm_bt(const bf16* __restrict__ Ah, const bf16* __restrict__ Al,
        const bf16* __restrict__ Bh, const bf16* __restrict__ Bl, float* __restrict__ C) {
    extern __shared__ char sm[];
    const uint32_t sb = smem_u32(sm);
    const int tid = threadIdx.x, lane = tid & 31, wid = tid >> 5;
    const int wm = wid >> 2, wn = wid & 3;
    const int bm = blockIdx.y * 128, bn = blockIdx.x * 256;

    float acc[4][8][4];
#pragma unroll
    for (int i = 0; i < 4; i++)
#pragma unroll
        for (int j = 0; j < 8; j++)
#pragma unroll
            for (int r = 0; r < 4; r++) acc[i][j][r] = 0.f;

    load_stage(Ah, Al, Bh, Bl, bm, bn, 0, sb, tid); cp_commit();
    load_stage(Ah, Al, Bh, Bl, bm, bn, 32, sb + STAGE, tid); cp_commit();
    const int lr = (lane & 7) + ((lane >> 3) & 1) * 8, lc16 = lane >> 4;

    for (int c = 0; c < 64; c++) {
        cp_wait<1>();
        __syncthreads();
        if (c + 2 < 64)
            load_stage(Ah, Al, Bh, Bl, bm, bn, (c + 2) * 32,
                       sb + (uint32_t)((c + 2) % 3) * STAGE, tid);
        cp_commit();
        const uint32_t stg = sb + (uint32_t)(c % 3) * STAGE;
#pragma unroll
        for (int ks = 0; ks < 2; ks++) {
            uint32_t ah[4][4], al[4][4];
#pragma unroll
            for (int mi = 0; mi < 4; mi++) {
                const int r = wm * 64 + mi * 16 + lr;
                const uint32_t so = swz64((uint32_t)(r * 64 + (ks * 2 + lc16) * 16));
                ldsm4(ah[mi][0], ah[mi][1], ah[mi][2], ah[mi][3], stg + AH_OFF + so);
                ldsm4(al[mi][0], al[mi][1], al[mi][2], al[mi][3], stg + AL_OFF + so);
            }
#pragma unroll
            for (int nj = 0; nj < 4; nj++) {
                const int r = wn * 64 + nj * 16 + lr;
                const uint32_t so = swz64((uint32_t)(r * 64 + (ks * 2 + lc16) * 16));
                uint32_t h0, h1, h2, h3, l0, l1, l2, l3;
                ldsm4(h0, h1, h2, h3, stg + BH_OFF + so);
                ldsm4(l0, l1, l2, l3, stg + BL_OFF + so);
                uint32_t b0h[2] = {h0, h2}, b1h[2] = {h1, h3};
                uint32_t b0l[2] = {l0, l2}, b1l[2] = {l1, l3};
#pragma unroll
                for (int mi = 0; mi < 4; mi++) {
                    mma16816(acc[mi][nj * 2], ah[mi], b0h);
                    mma16816(acc[mi][nj * 2], ah[mi], b0l);
                    mma16816(acc[mi][nj * 2], al[mi], b0h);
                    mma16816(acc[mi][nj * 2 + 1], ah[mi], b1h);
                    mma16816(acc[mi][nj * 2 + 1], ah[mi], b1l);
                    mma16816(acc[mi][nj * 2 + 1], al[mi], b1h);
                }
            }
        }
    }
    const int gr = lane >> 2, gc = (lane & 3) << 1;
#pragma unroll
    for (int mi = 0; mi < 4; mi++)
#pragma unroll
        for (int nn = 0; nn < 8; nn++) {
            const int row = bm + wm * 64 + mi * 16 + gr;
            const int col = bn + wn * 64 + nn * 8 + gc;
            *(float2*)(C + (size_t)row * 2048 + col) = make_float2(acc[mi][nn][0], acc[mi][nn][1]);
            *(float2*)(C + (size_t)(row + 8) * 2048 + col) = make_float2(acc[mi][nn][2], acc[mi][nn][3]);
        }
}

// ---- fp16 single-pass GEMM: C[M,2048] = A[M,2048]*B[2048,2048]^T (K-proj) ----
#define F16_A 0
#define F16_B 8192
#define F16_STG 24576
#define F16_SMEM (4 * F16_STG)   // 98304

__device__ __forceinline__ void f16_load(const __half* A, const __half* B,
                                         int bm, int bn, int kc, uint32_t stg, int tid) {
#pragma unroll
    for (int j = 0; j < 2; j++) {
        const int idx = j * 256 + tid, r = idx >> 2, c = idx & 3;
        cp16(stg + F16_A + swz64((uint32_t)(r * 64 + c * 16)),
             A + (size_t)(bm + r) * 2048 + kc + c * 8);
    }
#pragma unroll
    for (int j = 0; j < 4; j++) {
        const int idx = j * 256 + tid, r = idx >> 2, c = idx & 3;
        cp16(stg + F16_B + swz64((uint32_t)(r * 64 + c * 16)),
             B + (size_t)(bn + r) * 2048 + kc + c * 8);
    }
}

__global__ void __launch_bounds__(256, 1)
gemm_f16(const __half* __restrict__ A, const __half* __restrict__ B, float* __restrict__ C) {
    extern __shared__ char sm[];
    const uint32_t sb = smem_u32(sm);
    const int tid = threadIdx.x, lane = tid & 31, wid = tid >> 5;
    const int wm = wid >> 2, wn = wid & 3;
    const int bm = blockIdx.y * 128, bn = blockIdx.x * 256;

    float acc[4][8][4];
#pragma unroll
    for (int i = 0; i < 4; i++)
#pragma unroll
        for (int j = 0; j < 8; j++)
#pragma unroll
            for (int r = 0; r < 4; r++) acc[i][j][r] = 0.f;

    f16_load(A, B, bm, bn, 0, sb, tid); cp_commit();
    f16_load(A, B, bm, bn, 32, sb + F16_STG, tid); cp_commit();
    f16_load(A, B, bm, bn, 64, sb + 2 * F16_STG, tid); cp_commit();
    const int lr = (lane & 7) + ((lane >> 3) & 1) * 8, lc16 = lane >> 4;

    for (int c = 0; c < 64; c++) {
        cp_wait<2>();
        __syncthreads();
        if (c + 3 < 64)
            f16_load(A, B, bm, bn, (c + 3) * 32,
                     sb + (uint32_t)((c + 3) & 3) * F16_STG, tid);
        cp_commit();
        const uint32_t stg = sb + (uint32_t)(c & 3) * F16_STG;
#pragma unroll
        for (int ks = 0; ks < 2; ks++) {
            uint32_t a[4][4];
#pragma unroll
            for (int mi = 0; mi < 4; mi++) {
                const int r = wm * 64 + mi * 16 + lr;
                const uint32_t so = swz64((uint32_t)(r * 64 + (ks * 2 + lc16) * 16));
                ldsm4(a[mi][0], a[mi][1], a[mi][2], a[mi][3], stg + F16_A + so);
            }
#pragma unroll
            for (int nj = 0; nj < 4; nj++) {
                const int r = wn * 64 + nj * 16 + lr;
                const uint32_t so = swz64((uint32_t)(r * 64 + (ks * 2 + lc16) * 16));
                uint32_t h0, h1, h2, h3;
                ldsm4(h0, h1, h2, h3, stg + F16_B + so);
                uint32_t b0[2] = {h0, h2}, b1[2] = {h1, h3};
#pragma unroll
                for (int mi = 0; mi < 4; mi++) {
                    mmaf16(acc[mi][nj * 2], a[mi], b0);
                    mmaf16(acc[mi][nj * 2 + 1], a[mi], b1);
                }
            }
        }
    }
    const int gr = lane >> 2, gc = (lane & 3) << 1;
#pragma unroll
    for (int mi = 0; mi < 4; mi++)
#pragma unroll
        for (int nn = 0; nn < 8; nn++) {
            const int row = bm + wm * 64 + mi * 16 + gr;
            const int col = bn + wn * 64 + nn * 8 + gc;
            *(float2*)(C + (size_t)row * 2048 + col) = make_float2(acc[mi][nn][0], acc[mi][nn][1]);
            *(float2*)(C + (size_t)(row + 8) * 2048 + col) = make_float2(acc[mi][nn][2], acc[mi][nn][3]);
        }
}

// ---- batched N=64 GEMM: att[t, z*64+n] = mixed[z] @ wv_z^T, bf16 hi/lo out ----
#define N64_AH 0
#define N64_AL 8192
#define N64_BH 16384
#define N64_BL 20480
#define N64_STG 24576
#define N64_SMEM (3 * N64_STG)

__device__ __forceinline__ void n64_load(const bf16* Ah, const bf16* Al,
                                         const bf16* Bh, const bf16* Bl,
                                         int bm, int kc, uint32_t stg, int tid) {
#pragma unroll
    for (int j = 0; j < 2; j++) {
        const int idx = j * 256 + tid, r = idx >> 2, c = idx & 3;
        const uint32_t so = swz64((uint32_t)(r * 64 + c * 16));
        const size_t ga = (size_t)(bm + r) * 2048 + kc + c * 8;
        cp16(stg + N64_AH + so, Ah + ga);
        cp16(stg + N64_AL + so, Al + ga);
    }
    {
        const int r = tid >> 2, c = tid & 3;
        const uint32_t so = swz64((uint32_t)(r * 64 + c * 16));
        const size_t gb = (size_t)r * 2048 + kc + c * 8;
        cp16(stg + N64_BH + so, Bh + gb);
        cp16(stg + N64_BL + so, Bl + gb);
    }
}

__global__ void __launch_bounds__(256, 1)
gemm_n64(const bf16* __restrict__ Ah0, const bf16* __restrict__ Al0,
         const bf16* __restrict__ Bh0, const bf16* __restrict__ Bl0,
         bf16* __restrict__ Ch, bf16* __restrict__ Cl) {
    extern __shared__ char sm[];
    const uint32_t sb = smem_u32(sm);
    const int tid = threadIdx.x, lane = tid & 31, wid = tid >> 5;
    const int wm = wid >> 1, wn = wid & 1;
    const int bm = blockIdx.x * 128, z = blockIdx.y;
    const bf16* Ah = Ah0 + (size_t)z * T_ * 2048;
    const bf16* Al = Al0 + (size_t)z * T_ * 2048;
    const bf16* Bh = Bh0 + (size_t)z * 64 * 2048;
    const bf16* Bl = Bl0 + (size_t)z * 64 * 2048;

    float acc[2][4][4];
#pragma unroll
    for (int i = 0; i < 2; i++)
#pragma unroll
        for (int j = 0; j < 4; j++)
#pragma unroll
            for (int r = 0; r < 4; r++) acc[i][j][r] = 0.f;

    n64_load(Ah, Al, Bh, Bl, bm, 0, sb, tid); cp_commit();
    n64_load(Ah, Al, Bh, Bl, bm, 32, sb + N64_STG, tid); cp_commit();
    const int lr = (lane & 7) + ((lane >> 3) & 1) * 8, lc16 = lane >> 4;

    for (int c = 0; c < 64; c++) {
        cp_wait<1>();
        __syncthreads();
        if (c + 2 < 64)
            n64_load(Ah, Al, Bh, Bl, bm, (c + 2) * 32,
                     sb + (uint32_t)((c + 2) % 3) * N64_STG, tid);
        cp_commit();
        const uint32_t stg = sb + (uint32_t)(c % 3) * N64_STG;
#pragma unroll
        for (int ks = 0; ks < 2; ks++) {
            uint32_t ah[2][4], al[2][4];
#pragma unroll
            for (int mi = 0; mi < 2; mi++) {
                const int r = wm * 32 + mi * 16 + lr;
                const uint32_t so = swz64((uint32_t)(r * 64 + (ks * 2 + lc16) * 16));
                ldsm4(ah[mi][0], ah[mi][1], ah[mi][2], ah[mi][3], stg + N64_AH + so);
                ldsm4(al[mi][0], al[mi][1], al[mi][2], al[mi][3], stg + N64_AL + so);
            }
#pragma unroll
            for (int nj = 0; nj < 2; nj++) {
                const int r = wn * 32 + nj * 16 + lr;
                const uint32_t so = swz64((uint32_t)(r * 64 + (ks * 2 + lc16) * 16));
                uint32_t h0, h1, h2, h3, l0, l1, l2, l3;
                ldsm4(h0, h1, h2, h3, stg + N64_BH + so);
                ldsm4(l0, l1, l2, l3, stg + N64_BL + so);
                uint32_t b0h[2] = {h0, h2}, b1h[2] = {h1, h3};
                uint32_t b0l[2] = {l0, l2}, b1l[2] = {l1, l3};
#pragma unroll
                for (int mi = 0; mi < 2; mi++) {
                    mma16816(acc[mi][nj * 2], ah[mi], b0h);
                    mma16816(acc[mi][nj * 2], ah[mi], b0l);
                    mma16816(acc[mi][nj * 2], al[mi], b0h);
                    mma16816(acc[mi][nj * 2 + 1], ah[mi], b1h);
                    mma16816(acc[mi][nj * 2 + 1], ah[mi], b1l);
                    mma16816(acc[mi][nj * 2 + 1], al[mi], b1h);
                }
            }
        }
    }
    const int gr = lane >> 2, gc = (lane & 3) << 1;
#pragma unroll
    for (int mi = 0; mi < 2; mi++)
#pragma unroll
        for (int nn = 0; nn < 4; nn++) {
            const int row = bm + wm * 32 + mi * 16 + gr;
            const int col = wn * 32 + nn * 8 + gc;
            const size_t i0 = (size_t)z * 64 + (size_t)row * 2048 + col;
            const size_t i1 = i0 + (size_t)8 * 2048;
            float l0, l1, l2, l3;
            uint32_t h01 = pack_hi2(acc[mi][nn][0], acc[mi][nn][1], l0, l1);
            uint32_t h23 = pack_hi2(acc[mi][nn][2], acc[mi][nn][3], l2, l3);
            *(uint32_t*)(Ch + i0) = h01; *(uint32_t*)(Cl + i0) = pack2(l0, l1);
            *(uint32_t*)(Ch + i1) = h23; *(uint32_t*)(Cl + i1) = pack2(l2, l3);
        }
}

// ---- attnmix: scores (fp32) + softmax + char-mixing, one CTA per t ----
#define SCP 66
__global__ void __launch_bounds__(256)
attnmix(const float* __restrict__ q, const float* __restrict__ k,
        const float* __restrict__ chars, bf16* __restrict__ mh, bf16* __restrict__ ml) {
    const int t = blockIdx.x, tid = threadIdx.x;
    __shared__ float qsm[2048];
    __shared__ float sc[32 * SCP];
    __shared__ float at[32 * 64];
    ((float4*)qsm)[tid] = ((const float4*)(q + (size_t)t * 2048))[tid];
    ((float4*)qsm)[tid + 256] = ((const float4*)(q + (size_t)t * 2048))[tid + 256];
    __syncthreads();
    const int jlo = (t >= 7) ? 0 : (7 - t) * 8;
    {
        const int j = tid >> 2, hq = tid & 3;
        const float* kr = k + (size_t)((t - 7) * 8 + j) * 2048;
#pragma unroll
        for (int i = 0; i < 8; i++) {
            const int h = hq * 8 + i;
            float s = 0.f;
            if (j >= jlo) {
                const float4* k4 = (const float4*)(kr + h * 64);
                const float4* q4 = (const float4*)(qsm + h * 64);
#pragma unroll
                for (int d = 0; d < 16; d++) {
                    float4 a = q4[d], b = k4[d];
                    s = fmaf(a.x, b.x, s); s = fmaf(a.y, b.y, s);
                    s = fmaf(a.z, b.z, s); s = fmaf(a.w, b.w, s);
                }
                s *= 0.125f;
            }
            sc[h * SCP + j] = s;
        }
    }
    __syncthreads();
    {
        const int r = tid >> 3, l8 = tid & 7;
        float vals[8], m = -1e30f;
#pragma unroll
        for (int i = 0; i < 8; i++) { vals[i] = sc[r * SCP + l8 + i * 8]; m = fmaxf(m, vals[i]); }
#pragma unroll
        for (int o = 4; o; o >>= 1) m = fmaxf(m, __shfl_xor_sync(0xffffffffu, m, o));
        float s = 0.f;
#pragma unroll
        for (int i = 0; i < 8; i++) { vals[i] = expf(vals[i] - m); s += vals[i]; }
#pragma unroll
        for (int o = 4; o; o >>= 1) s += __shfl_xor_sync(0xffffffffu, s, o);
        const float inv = 1.f / s;
#pragma unroll
        for (int i = 0; i < 8; i++) at[r * 64 + l8 + i * 8] = vals[i] * inv;
    }
    __syncthreads();
    {
        const int hg = tid >> 5, cg = tid & 31;
        const float* cbase = chars + (size_t)((t - 7) * 8) * 2048;
        for (int cb = 0; cb < 8; cb++) {
            const int c0 = cb * 256 + cg * 8;
            float acc[4][8];
#pragma unroll
            for (int a = 0; a < 4; a++)
#pragma unroll
                for (int b = 0; b < 8; b++) acc[a][b] = 0.f;
            for (int j = jlo; j < 64; j++) {
                const float4* cw = (const float4*)(cbase + (size_t)j * 2048 + c0);
                float4 v0 = cw[0], v1 = cw[1];
#pragma unroll
                for (int hh = 0; hh < 4; hh++) {
                    const float w = at[(hg * 4 + hh) * 64 + j];
                    acc[hh][0] = fmaf(w, v0.x, acc[hh][0]); acc[hh][1] = fmaf(w, v0.y, acc[hh][1]);
                    acc[hh][2] = fmaf(w, v0.z, acc[hh][2]); acc[hh][3] = fmaf(w, v0.w, acc[hh][3]);
                    acc[hh][4] = fmaf(w, v1.x, acc[hh][4]); acc[hh][5] = fmaf(w, v1.y, acc[hh][5]);
                    acc[hh][6] = fmaf(w, v1.z, acc[hh][6]); acc[hh][7] = fmaf(w, v1.w, acc[hh][7]);
                }
            }
#pragma unroll
            for (int hh = 0; hh < 4; hh++) {
                const int h = hg * 4 + hh;
                const size_t o = ((size_t)h * T_ + t) * 2048 + c0;
                uint32_t hv[4], lv[4];
#pragma unroll
                for (int i = 0; i < 4; i++) {
                    float l0, l1;
                    hv[i] = pack_hi2(acc[hh][i * 2], acc[hh][i * 2 + 1], l0, l1);
                    lv[i] = pack2(l0, l1);
                }
                *(uint4*)(mh + o) = make_uint4(hv[0], hv[1], hv[2], hv[3]);
                *(uint4*)(ml + o) = make_uint4(lv[0], lv[1], lv[2], lv[3]);
            }
        }
    }
}

extern "C" void kernel_launch(void* const* d_in, const int* in_sizes, int n_in,
                              void* d_out, int out_size) {
    const float* x = (const float*)d_in[0];
    const float* chars = (const float*)d_in[1];
    const float* wq = (const float*)d_in[2];
    const float* wk = (const float*)d_in[3];
    const float* wv = (const float*)d_in[4];
    const float* wo = (const float*)d_in[5];
    float* out = (float*)d_out;

    float *q, *k;
    __half *chf, *wkf;
    bf16 *xh, *xl, *wqh, *wql, *wvh, *wvl, *woh, *wol, *mxh, *mxl, *ath, *atl;
    cudaGetSymbolAddress((void**)&q, g_q);     cudaGetSymbolAddress((void**)&k, g_k);
    cudaGetSymbolAddress((void**)&chf, g_chf); cudaGetSymbolAddress((void**)&wkf, g_wkf);
    cudaGetSymbolAddress((void**)&xh, g_xh);   cudaGetSymbolAddress((void**)&xl, g_xl);
    cudaGetSymbolAddress((void**)&wqh, g_wqh); cudaGetSymbolAddress((void**)&wql, g_wql);
    cudaGetSymbolAddress((void**)&wvh, g_wvh); cudaGetSymbolAddress((void**)&wvl, g_wvl);
    cudaGetSymbolAddress((void**)&woh, g_woh); cudaGetSymbolAddress((void**)&wol, g_wol);
    cudaGetSymbolAddress((void**)&mxh, g_mxh); cudaGetSymbolAddress((void**)&mxl, g_mxl);
    cudaGetSymbolAddress((void**)&ath, g_ath); cudaGetSymbolAddress((void**)&atl, g_atl);

    cudaFuncSetAttribute(gemm_bt, cudaFuncAttributeMaxDynamicSharedMemorySize, GEMM_SMEM);
    cudaFuncSetAttribute(gemm_f16, cudaFuncAttributeMaxDynamicSharedMemorySize, F16_SMEM);
    cudaFuncSetAttribute(gemm_n64, cudaFuncAttributeMaxDynamicSharedMemorySize, N64_SMEM);

    auto cvt = [](const float* s, bf16* h, bf16* l, int n) {
        cvt_split<<<(n / 4 + 255) / 256, 256>>>((const float4*)s, (uint2*)h, (uint2*)l, n / 4);
    };
    cvt(x, xh, xl, T_ * DIM_);
    cvt(wq, wqh, wql, DIM_ * DIM_);
    cvt(wv, wvh, wvl, DIM_ * DIM_);
    cvt(wo, woh, wol, DIM_ * DIM_);
    cvt_f16<<<(T_ * 8 * DIM_ / 4 + 255) / 256, 256>>>((const float4*)chars, (uint2*)chf, T_ * 8 * DIM_ / 4);
    cvt_f16<<<(DIM_ * DIM_ / 4 + 255) / 256, 256>>>((const float4*)wk, (uint2*)wkf, DIM_ * DIM_ / 4);

    gemm_bt<<<dim3(8, 8), 256, GEMM_SMEM>>>(xh, xl, wqh, wql, q);          // q
    gemm_f16<<<dim3(8, 64), 256, F16_SMEM>>>(chf, wkf, k);                 // k (fp16 1-pass)
    attnmix<<<T_, 256>>>(q, k, chars, mxh, mxl);                           // scores+softmax+mix
    gemm_n64<<<dim3(8, 32), 256, N64_SMEM>>>(mxh, mxl, wvh, wvl, ath, atl); // v-proj
    gemm_bt<<<dim3(8, 8), 256, GEMM_SMEM>>>(ath, atl, woh, wol, out);      // o-proj
}

// round 10
// speedup vs baseline: 3.6106x; 1.3418x over previous
#include <cuda_runtime.h>
#include <cuda_fp16.h>
#include <cstdint>
#include <math.h>

#define T_ 1024
#define DIM_ 2048
#define NH_ 32

__device__ float g_q[T_ * DIM_];
__device__ float g_k[T_ * 8 * DIM_];
__device__ __align__(16) __half g_xf[T_ * DIM_];
__device__ __align__(16) __half g_chf[T_ * 8 * DIM_];
__device__ __align__(16) __half g_wqf[DIM_ * DIM_];
__device__ __align__(16) __half g_wkf[DIM_ * DIM_];
__device__ __align__(16) __half g_wvf[DIM_ * DIM_];
__device__ __align__(16) __half g_wof[DIM_ * DIM_];
__device__ __align__(16) __half g_mxf[(size_t)NH_ * T_ * DIM_];
__device__ __align__(16) __half g_attf[T_ * DIM_];

__device__ __forceinline__ uint32_t smem_u32(const void* p) {
    uint32_t a;
    asm("{ .reg .u64 t; cvta.to.shared.u64 t, %1; cvt.u32.u64 %0, t; }" : "=r"(a) : "l"(p));
    return a;
}
__device__ __forceinline__ uint32_t swz64(uint32_t o) { return o ^ ((o >> 3) & 0x30); }
__device__ __forceinline__ void ldsm4(uint32_t& r0, uint32_t& r1, uint32_t& r2,
                                      uint32_t& r3, uint32_t a) {
    asm volatile("ldmatrix.sync.aligned.m8n8.x4.shared.b16 {%0,%1,%2,%3}, [%4];"
                 : "=r"(r0), "=r"(r1), "=r"(r2), "=r"(r3) : "r"(a));
}
__device__ __forceinline__ void mmaf16(float* c, const uint32_t* a, const uint32_t* b) {
    asm volatile("mma.sync.aligned.m16n8k16.row.col.f32.f16.f16.f32 "
                 "{%0,%1,%2,%3}, {%4,%5,%6,%7}, {%8,%9}, {%0,%1,%2,%3};"
                 : "+f"(c[0]), "+f"(c[1]), "+f"(c[2]), "+f"(c[3])
                 : "r"(a[0]), "r"(a[1]), "r"(a[2]), "r"(a[3]), "r"(b[0]), "r"(b[1]));
}
__device__ __forceinline__ void cp16(uint32_t s, const void* g) {
    asm volatile("cp.async.cg.shared.global [%0], [%1], 16;" :: "r"(s), "l"(g) : "memory");
}
__device__ __forceinline__ void cp_commit() { asm volatile("cp.async.commit_group;" ::: "memory"); }
template <int N> __device__ __forceinline__ void cp_wait() {
    asm volatile("cp.async.wait_group %0;" :: "n"(N) : "memory");
}

__global__ void __launch_bounds__(256)
cvt_f16(const float4* __restrict__ src, uint2* __restrict__ d, int n4) {
    for (int i = blockIdx.x * blockDim.x + threadIdx.x; i < n4; i += gridDim.x * blockDim.x) {
        float4 f = src[i];
        __half2 a = __float22half2_rn(make_float2(f.x, f.y));
        __half2 b = __float22half2_rn(make_float2(f.z, f.w));
        d[i] = make_uint2(*(uint32_t*)&a, *(uint32_t*)&b);
    }
}

// ---- fp16 GEMM, tile 128x256 (K-projection; M=8192) ----
#define F16_A 0
#define F16_B 8192
#define F16_STG 24576
#define F16_SMEM (4 * F16_STG)

__device__ __forceinline__ void f16_load(const __half* A, const __half* B,
                                         int bm, int bn, int kc, uint32_t stg, int tid) {
#pragma unroll
    for (int j = 0; j < 2; j++) {
        const int idx = j * 256 + tid, r = idx >> 2, c = idx & 3;
        cp16(stg + F16_A + swz64((uint32_t)(r * 64 + c * 16)),
             A + (size_t)(bm + r) * 2048 + kc + c * 8);
    }
#pragma unroll
    for (int j = 0; j < 4; j++) {
        const int idx = j * 256 + tid, r = idx >> 2, c = idx & 3;
        cp16(stg + F16_B + swz64((uint32_t)(r * 64 + c * 16)),
             B + (size_t)(bn + r) * 2048 + kc + c * 8);
    }
}

__global__ void __launch_bounds__(256, 1)
gemm_f16(const __half* __restrict__ A, const __half* __restrict__ B, float* __restrict__ C) {
    extern __shared__ char sm[];
    const uint32_t sb = smem_u32(sm);
    const int tid = threadIdx.x, lane = tid & 31, wid = tid >> 5;
    const int wm = wid >> 2, wn = wid & 3;
    const int bm = blockIdx.y * 128, bn = blockIdx.x * 256;

    float acc[4][8][4];
#pragma unroll
    for (int i = 0; i < 4; i++)
#pragma unroll
        for (int j = 0; j < 8; j++)
#pragma unroll
            for (int r = 0; r < 4; r++) acc[i][j][r] = 0.f;

    f16_load(A, B, bm, bn, 0, sb, tid); cp_commit();
    f16_load(A, B, bm, bn, 32, sb + F16_STG, tid); cp_commit();
    f16_load(A, B, bm, bn, 64, sb + 2 * F16_STG, tid); cp_commit();
    const int lr = (lane & 7) + ((lane >> 3) & 1) * 8, lc16 = lane >> 4;

    for (int c = 0; c < 64; c++) {
        cp_wait<2>();
        __syncthreads();
        if (c + 3 < 64)
            f16_load(A, B, bm, bn, (c + 3) * 32, sb + (uint32_t)((c + 3) & 3) * F16_STG, tid);
        cp_commit();
        const uint32_t stg = sb + (uint32_t)(c & 3) * F16_STG;
#pragma unroll
        for (int ks = 0; ks < 2; ks++) {
            uint32_t a[4][4];
#pragma unroll
            for (int mi = 0; mi < 4; mi++) {
                const int r = wm * 64 + mi * 16 + lr;
                const uint32_t so = swz64((uint32_t)(r * 64 + (ks * 2 + lc16) * 16));
                ldsm4(a[mi][0], a[mi][1], a[mi][2], a[mi][3], stg + F16_A + so);
            }
#pragma unroll
            for (int nj = 0; nj < 4; nj++) {
                const int r = wn * 64 + nj * 16 + lr;
                const uint32_t so = swz64((uint32_t)(r * 64 + (ks * 2 + lc16) * 16));
                uint32_t h0, h1, h2, h3;
                ldsm4(h0, h1, h2, h3, stg + F16_B + so);
                uint32_t b0[2] = {h0, h2}, b1[2] = {h1, h3};
#pragma unroll
                for (int mi = 0; mi < 4; mi++) {
                    mmaf16(acc[mi][nj * 2], a[mi], b0);
                    mmaf16(acc[mi][nj * 2 + 1], a[mi], b1);
                }
            }
        }
    }
    const int gr = lane >> 2, gc = (lane & 3) << 1;
#pragma unroll
    for (int mi = 0; mi < 4; mi++)
#pragma unroll
        for (int nn = 0; nn < 8; nn++) {
            const int row = bm + wm * 64 + mi * 16 + gr;
            const int col = bn + wn * 64 + nn * 8 + gc;
            *(float2*)(C + (size_t)row * 2048 + col) = make_float2(acc[mi][nn][0], acc[mi][nn][1]);
            *(float2*)(C + (size_t)(row + 8) * 2048 + col) = make_float2(acc[mi][nn][2], acc[mi][nn][3]);
        }
}

// ---- fp16 GEMM, tile 128x128 (Q / O projections; M=1024 -> 128 CTAs) ----
#define S_A 0
#define S_B 8192
#define S_STG 16384
#define S_SMEM (4 * S_STG)

__device__ __forceinline__ void s_load(const __half* A, const __half* B,
                                       int bm, int bn, int kc, uint32_t stg, int tid) {
#pragma unroll
    for (int j = 0; j < 2; j++) {
        const int idx = j * 256 + tid, r = idx >> 2, c = idx & 3;
        const uint32_t so = swz64((uint32_t)(r * 64 + c * 16));
        cp16(stg + S_A + so, A + (size_t)(bm + r) * 2048 + kc + c * 8);
        cp16(stg + S_B + so, B + (size_t)(bn + r) * 2048 + kc + c * 8);
    }
}

__global__ void __launch_bounds__(256, 1)
gemm_f16s(const __half* __restrict__ A, const __half* __restrict__ B, float* __restrict__ C) {
    extern __shared__ char sm[];
    const uint32_t sb = smem_u32(sm);
    const int tid = threadIdx.x, lane = tid & 31, wid = tid >> 5;
    const int wm = wid >> 2, wn = wid & 3;     // warp tile 64x32
    const int bm = blockIdx.y * 128, bn = blockIdx.x * 128;

    float acc[4][4][4];
#pragma unroll
    for (int i = 0; i < 4; i++)
#pragma unroll
        for (int j = 0; j < 4; j++)
#pragma unroll
            for (int r = 0; r < 4; r++) acc[i][j][r] = 0.f;

    s_load(A, B, bm, bn, 0, sb, tid); cp_commit();
    s_load(A, B, bm, bn, 32, sb + S_STG, tid); cp_commit();
    s_load(A, B, bm, bn, 64, sb + 2 * S_STG, tid); cp_commit();
    const int lr = (lane & 7) + ((lane >> 3) & 1) * 8, lc16 = lane >> 4;

    for (int c = 0; c < 64; c++) {
        cp_wait<2>();
        __syncthreads();
        if (c + 3 < 64)
            s_load(A, B, bm, bn, (c + 3) * 32, sb + (uint32_t)((c + 3) & 3) * S_STG, tid);
        cp_commit();
        const uint32_t stg = sb + (uint32_t)(c & 3) * S_STG;
#pragma unroll
        for (int ks = 0; ks < 2; ks++) {
            uint32_t a[4][4];
#pragma unroll
            for (int mi = 0; mi < 4; mi++) {
                const int r = wm * 64 + mi * 16 + lr;
                const uint32_t so = swz64((uint32_t)(r * 64 + (ks * 2 + lc16) * 16));
                ldsm4(a[mi][0], a[mi][1], a[mi][2], a[mi][3], stg + S_A + so);
            }
#pragma unroll
            for (int nj = 0; nj < 2; nj++) {
                const int r = wn * 32 + nj * 16 + lr;
                const uint32_t so = swz64((uint32_t)(r * 64 + (ks * 2 + lc16) * 16));
                uint32_t h0, h1, h2, h3;
                ldsm4(h0, h1, h2, h3, stg + S_B + so);
                uint32_t b0[2] = {h0, h2}, b1[2] = {h1, h3};
#pragma unroll
                for (int mi = 0; mi < 4; mi++) {
                    mmaf16(acc[mi][nj * 2], a[mi], b0);
                    mmaf16(acc[mi][nj * 2 + 1], a[mi], b1);
                }
            }
        }
    }
    const int gr = lane >> 2, gc = (lane & 3) << 1;
#pragma unroll
    for (int mi = 0; mi < 4; mi++)
#pragma unroll
        for (int nn = 0; nn < 4; nn++) {
            const int row = bm + wm * 64 + mi * 16 + gr;
            const int col = bn + wn * 32 + nn * 8 + gc;
            *(float2*)(C + (size_t)row * 2048 + col) = make_float2(acc[mi][nn][0], acc[mi][nn][1]);
            *(float2*)(C + (size_t)(row + 8) * 2048 + col) = make_float2(acc[mi][nn][2], acc[mi][nn][3]);
        }
}

// ---- batched N=64 fp16 GEMM: att[t, z*64+n] = mixed[z] @ wv_z^T, fp16 out ----
#define N64_A 0
#define N64_B 8192
#define N64_STG 12288
#define N64_SMEM (4 * N64_STG)

__device__ __forceinline__ void n64_load(const __half* A, const __half* B,
                                         int bm, int kc, uint32_t stg, int tid) {
#pragma unroll
    for (int j = 0; j < 2; j++) {
        const int idx = j * 256 + tid, r = idx >> 2, c = idx & 3;
        cp16(stg + N64_A + swz64((uint32_t)(r * 64 + c * 16)),
             A + (size_t)(bm + r) * 2048 + kc + c * 8);
    }
    if (tid < 256) {
        const int r = tid >> 2, c = tid & 3;
        if (r < 64)
            cp16(stg + N64_B + swz64((uint32_t)(r * 64 + c * 16)),
                 B + (size_t)r * 2048 + kc + c * 8);
    }
}

__global__ void __launch_bounds__(256, 1)
gemm_n64(const __half* __restrict__ A0, const __half* __restrict__ B0,
         __half* __restrict__ Co) {
    extern __shared__ char sm[];
    const uint32_t sb = smem_u32(sm);
    const int tid = threadIdx.x, lane = tid & 31, wid = tid >> 5;
    const int wm = wid >> 1, wn = wid & 1;     // warp tile 32x32
    const int bm = blockIdx.x * 128, z = blockIdx.y;
    const __half* A = A0 + (size_t)z * T_ * 2048;
    const __half* B = B0 + (size_t)z * 64 * 2048;

    float acc[2][4][4];
#pragma unroll
    for (int i = 0; i < 2; i++)
#pragma unroll
        for (int j = 0; j < 4; j++)
#pragma unroll
            for (int r = 0; r < 4; r++) acc[i][j][r] = 0.f;

    n64_load(A, B, bm, 0, sb, tid); cp_commit();
    n64_load(A, B, bm, 32, sb + N64_STG, tid); cp_commit();
    n64_load(A, B, bm, 64, sb + 2 * N64_STG, tid); cp_commit();
    const int lr = (lane & 7) + ((lane >> 3) & 1) * 8, lc16 = lane >> 4;

    for (int c = 0; c < 64; c++) {
        cp_wait<2>();
        __syncthreads();
        if (c + 3 < 64)
            n64_load(A, B, bm, (c + 3) * 32, sb + (uint32_t)((c + 3) & 3) * N64_STG, tid);
        cp_commit();
        const uint32_t stg = sb + (uint32_t)(c & 3) * N64_STG;
#pragma unroll
        for (int ks = 0; ks < 2; ks++) {
            uint32_t a[2][4];
#pragma unroll
            for (int mi = 0; mi < 2; mi++) {
                const int r = wm * 32 + mi * 16 + lr;
                const uint32_t so = swz64((uint32_t)(r * 64 + (ks * 2 + lc16) * 16));
                ldsm4(a[mi][0], a[mi][1], a[mi][2], a[mi][3], stg + N64_A + so);
            }
#pragma unroll
            for (int nj = 0; nj < 2; nj++) {
                const int r = wn * 32 + nj * 16 + lr;
                const uint32_t so = swz64((uint32_t)(r * 64 + (ks * 2 + lc16) * 16));
                uint32_t h0, h1, h2, h3;
                ldsm4(h0, h1, h2, h3, stg + N64_B + so);
                uint32_t b0[2] = {h0, h2}, b1[2] = {h1, h3};
#pragma unroll
                for (int mi = 0; mi < 2; mi++) {
                    mmaf16(acc[mi][nj * 2], a[mi], b0);
                    mmaf16(acc[mi][nj * 2 + 1], a[mi], b1);
                }
            }
        }
    }
    const int gr = lane >> 2, gc = (lane & 3) << 1;
#pragma unroll
    for (int mi = 0; mi < 2; mi++)
#pragma unroll
        for (int nn = 0; nn < 4; nn++) {
            const int row = bm + wm * 32 + mi * 16 + gr;
            const int col = wn * 32 + nn * 8 + gc;
            const size_t i0 = (size_t)row * 2048 + z * 64 + col;
            const size_t i1 = i0 + (size_t)8 * 2048;
            __half2 p0 = __float22half2_rn(make_float2(acc[mi][nn][0], acc[mi][nn][1]));
            __half2 p1 = __float22half2_rn(make_float2(acc[mi][nn][2], acc[mi][nn][3]));
            *(uint32_t*)(Co + i0) = *(uint32_t*)&p0;
            *(uint32_t*)(Co + i1) = *(uint32_t*)&p1;
        }
}

// ---- attnmix: scores (fp32) + softmax + char-mixing -> fp16 mixed ----
// scores[h][j] = q[t,h]·k[(t-7)*8+j, h]/8; padded j (p<0) -> score 0, matching
// reference zero-padded swa. RoPE drops out (q,k share per-t rotation; v unrotated).
#define SCP 66
__global__ void __launch_bounds__(256)
attnmix(const float* __restrict__ q, const float* __restrict__ k,
        const float* __restrict__ chars, __half* __restrict__ mx) {
    const int t = blockIdx.x, tid = threadIdx.x;
    __shared__ float qsm[2048];
    __shared__ float sc[32 * SCP];
    __shared__ float at[32 * 64];
    ((float4*)qsm)[tid] = ((const float4*)(q + (size_t)t * 2048))[tid];
    ((float4*)qsm)[tid + 256] = ((const float4*)(q + (size_t)t * 2048))[tid + 256];
    __syncthreads();
    const int jlo = (t >= 7) ? 0 : (7 - t) * 8;
    {
        const int j = tid >> 2, hq = tid & 3;
        const float* kr = k + (size_t)((t - 7) * 8 + j) * 2048;
#pragma unroll
        for (int i = 0; i < 8; i++) {
            const int h = hq * 8 + i;
            float s = 0.f;
            if (j >= jlo) {
                const float4* k4 = (const float4*)(kr + h * 64);
                const float4* q4 = (const float4*)(qsm + h * 64);
#pragma unroll
                for (int d = 0; d < 16; d++) {
                    float4 a = q4[d], b = k4[d];
                    s = fmaf(a.x, b.x, s); s = fmaf(a.y, b.y, s);
                    s = fmaf(a.z, b.z, s); s = fmaf(a.w, b.w, s);
                }
                s *= 0.125f;
            }
            sc[h * SCP + j] = s;
        }
    }
    __syncthreads();
    {
        const int r = tid >> 3, l8 = tid & 7;
        float vals[8], m = -1e30f;
#pragma unroll
        for (int i = 0; i < 8; i++) { vals[i] = sc[r * SCP + l8 + i * 8]; m = fmaxf(m, vals[i]); }
#pragma unroll
        for (int o = 4; o; o >>= 1) m = fmaxf(m, __shfl_xor_sync(0xffffffffu, m, o));
        float s = 0.f;
#pragma unroll
        for (int i = 0; i < 8; i++) { vals[i] = expf(vals[i] - m); s += vals[i]; }
#pragma unroll
        for (int o = 4; o; o >>= 1) s += __shfl_xor_sync(0xffffffffu, s, o);
        const float inv = 1.f / s;
#pragma unroll
        for (int i = 0; i < 8; i++) at[r * 64 + l8 + i * 8] = vals[i] * inv;
    }
    __syncthreads();
    {
        const int hg = tid >> 6, cg = tid & 63;   // 4 head-groups x 8 heads; 64 col-groups
        const float* cbase = chars + (size_t)((t - 7) * 8) * 2048;
#pragma unroll
        for (int cb = 0; cb < 4; cb++) {
            const int c0 = cb * 512 + cg * 8;
            float acc[8][8];
#pragma unroll
            for (int a = 0; a < 8; a++)
#pragma unroll
                for (int b = 0; b < 8; b++) acc[a][b] = 0.f;
            for (int j = jlo; j < 64; j++) {
                const float4* cw = (const float4*)(cbase + (size_t)j * 2048 + c0);
                float4 v0 = cw[0], v1 = cw[1];
#pragma unroll
                for (int hh = 0; hh < 8; hh++) {
                    const float w = at[(hg * 8 + hh) * 64 + j];
                    acc[hh][0] = fmaf(w, v0.x, acc[hh][0]); acc[hh][1] = fmaf(w, v0.y, acc[hh][1]);
                    acc[hh][2] = fmaf(w, v0.z, acc[hh][2]); acc[hh][3] = fmaf(w, v0.w, acc[hh][3]);
                    acc[hh][4] = fmaf(w, v1.x, acc[hh][4]); acc[hh][5] = fmaf(w, v1.y, acc[hh][5]);
                    acc[hh][6] = fmaf(w, v1.z, acc[hh][6]); acc[hh][7] = fmaf(w, v1.w, acc[hh][7]);
                }
            }
#pragma unroll
            for (int hh = 0; hh < 8; hh++) {
                const int h = hg * 8 + hh;
                const size_t o = ((size_t)h * T_ + t) * 2048 + c0;
                __half2 p0 = __float22half2_rn(make_float2(acc[hh][0], acc[hh][1]));
                __half2 p1 = __float22half2_rn(make_float2(acc[hh][2], acc[hh][3]));
                __half2 p2 = __float22half2_rn(make_float2(acc[hh][4], acc[hh][5]));
                __half2 p3 = __float22half2_rn(make_float2(acc[hh][6], acc[hh][7]));
                *(uint4*)(mx + o) = make_uint4(*(uint32_t*)&p0, *(uint32_t*)&p1,
                                               *(uint32_t*)&p2, *(uint32_t*)&p3);
            }
        }
    }
}

extern "C" void kernel_launch(void* const* d_in, const int* in_sizes, int n_in,
                              void* d_out, int out_size) {
    const float* x = (const float*)d_in[0];
    const float* chars = (const float*)d_in[1];
    const float* wq = (const float*)d_in[2];
    const float* wk = (const float*)d_in[3];
    const float* wv = (const float*)d_in[4];
    const float* wo = (const float*)d_in[5];
    float* out = (float*)d_out;

    float *q, *k;
    __half *xf, *chf, *wqf, *wkf, *wvf, *wof, *mxf, *attf;
    cudaGetSymbolAddress((void**)&q, g_q);     cudaGetSymbolAddress((void**)&k, g_k);
    cudaGetSymbolAddress((void**)&xf, g_xf);   cudaGetSymbolAddress((void**)&chf, g_chf);
    cudaGetSymbolAddress((void**)&wqf, g_wqf); cudaGetSymbolAddress((void**)&wkf, g_wkf);
    cudaGetSymbolAddress((void**)&wvf, g_wvf); cudaGetSymbolAddress((void**)&wof, g_wof);
    cudaGetSymbolAddress((void**)&mxf, g_mxf); cudaGetSymbolAddress((void**)&attf, g_attf);

    cudaFuncSetAttribute(gemm_f16, cudaFuncAttributeMaxDynamicSharedMemorySize, F16_SMEM);
    cudaFuncSetAttribute(gemm_f16s, cudaFuncAttributeMaxDynamicSharedMemorySize, S_SMEM);
    cudaFuncSetAttribute(gemm_n64, cudaFuncAttributeMaxDynamicSharedMemorySize, N64_SMEM);

    auto cvt = [](const float* s, __half* d, int n) {
        cvt_f16<<<(n / 4 + 255) / 256, 256>>>((const float4*)s, (uint2*)d, n / 4);
    };
    cvt(x, xf, T_ * DIM_);
    cvt(chars, chf, T_ * 8 * DIM_);
    cvt(wq, wqf, DIM_ * DIM_);
    cvt(wk, wkf, DIM_ * DIM_);
    cvt(wv, wvf, DIM_ * DIM_);
    cvt(wo, wof, DIM_ * DIM_);

    gemm_f16s<<<dim3(16, 8), 256, S_SMEM>>>(xf, wqf, q);        // q proj (128 CTAs)
    gemm_f16<<<dim3(8, 64), 256, F16_SMEM>>>(chf, wkf, k);      // k proj
    attnmix<<<T_, 256>>>(q, k, chars, mxf);                     // scores+softmax+mix
    gemm_n64<<<dim3(8, 32), 256, N64_SMEM>>>(mxf, wvf, attf);   // v proj (batched, N=64)
    gemm_f16s<<<dim3(16, 8), 256, S_SMEM>>>(attf, wof, out);    // o proj (128 CTAs)
}